// round 13
// baseline (speedup 1.0000x reference)
#include <cuda_runtime.h>
#include <math.h>

#define Bn 64
#define Cn 2048
#define Qn 128
#define Dn 128
#define MASK_VAL (-1e30f)

// ---------------- scratch ----------------
__device__ float g_score[(size_t)Bn*Cn*Qn];
__device__ float g_Beff [(size_t)Bn*Dn*Qn];
__device__ float g_bq   [Bn*Qn];
__device__ float g_rowmax[Bn*Cn];
__device__ float g_rowsum[Bn*Cn];
__device__ float g_colpm[Bn*16*Qn];
__device__ float g_colps[Bn*16*Qn];
__device__ float g_colmax[Bn*Qn];
__device__ float g_colsum[Bn*Qn];
__device__ float g_tmp_part[(size_t)Bn*4*Qn*Dn];
__device__ float g_tmp [(size_t)Bn*Qn*Dn];
__device__ float g_bias2[Bn*Dn];
__device__ float g_c2q [(size_t)Bn*Cn*Dn];
__device__ float g_q2c [(size_t)Bn*Cn*Dn];
__device__ float g_feats[(size_t)Bn*Cn*Dn];
__device__ float g_cqaWT[512*128];
__device__ float g_ccWT [128*128];

// ---------------- tf32 helpers ----------------
__device__ __forceinline__ unsigned cvt_tf32(float x){
  unsigned u; asm("cvt.rna.tf32.f32 %0, %1;" : "=r"(u) : "f"(x)); return u;
}
__device__ __forceinline__ float tf32_hi(float x){ return __uint_as_float(cvt_tf32(x)); }

#define MMA_TF32(D, A0,A1,A2,A3, B0,B1) \
  asm volatile("mma.sync.aligned.m16n8k8.row.col.f32.tf32.tf32.f32 " \
      "{%0,%1,%2,%3}, {%4,%5,%6,%7}, {%8,%9}, {%0,%1,%2,%3};" \
      : "+f"(D[0]), "+f"(D[1]), "+f"(D[2]), "+f"(D[3]) \
      : "r"(A0), "r"(A1), "r"(A2), "r"(A3), "r"(B0), "r"(B1))

// ---- swizzled fragment tile [rows][32]:
// element k (0..15) of row n stored at quad ((k&3) + (n&7) + (n>>3)) & 7, offset k>>2.

__device__ __forceinline__ void storeB8(float (*T)[32], int bseg, int bkl, const float* v8){
  int bq = bkl >> 2, bc = bkl & 3;
  int e0 = bseg*8;
  #pragma unroll
  for (int e = 0; e < 8; e++)
    T[e0+e][((bc + e + bseg) & 7)*4 + bq] = v8[e];
}
__device__ __forceinline__ void storeA2(float (*T)[32], int arow, int aj0,
                                        const float4& v0, const float4& v1){
  int ga = (arow & 7) + (arow >> 3);
  const float* p0 = (const float*)&v0;
  const float* p1 = (const float*)&v1;
  #pragma unroll
  for (int t = 0; t < 4; t++){
    T[arow][((t + ga) & 7)*4 + aj0]     = p0[t];
    T[arow][((t + ga) & 7)*4 + aj0 + 1] = p1[t];
  }
}

// Per-warp 32x64 tile MMA over a k16 chunk, swizzled tiles.
__device__ __forceinline__ void mma_k16(const float (*As)[32], const float (*Bs)[32],
                                        float acc[2][8][4], int mb, int nb, int grp, int qd){
  int baseq = qd + grp;
  int mh = mb >> 3, nh = nb >> 3;
  float4 va[2][2];
  #pragma unroll
  for (int mi = 0; mi < 2; mi++){
    int r = mb + mi*16 + grp;
    va[mi][0] = *(const float4*)&As[r][((baseq + mh + mi*2) & 7)*4];
    va[mi][1] = *(const float4*)&As[r+8][((baseq + mh + mi*2 + 1) & 7)*4];
  }
  float4 vb[8];
  #pragma unroll
  for (int ni = 0; ni < 8; ni++){
    int n = nb + ni*8 + grp;
    vb[ni] = *(const float4*)&Bs[n][((baseq + nh + ni) & 7)*4];
  }
  #pragma unroll
  for (int mi = 0; mi < 2; mi++)
    #pragma unroll
    for (int ni = 0; ni < 8; ni++){
      MMA_TF32(acc[mi][ni],
        __float_as_uint(va[mi][0].x), __float_as_uint(va[mi][1].x),
        __float_as_uint(va[mi][0].y), __float_as_uint(va[mi][1].y),
        __float_as_uint(vb[ni].x),    __float_as_uint(vb[ni].y));
      MMA_TF32(acc[mi][ni],
        __float_as_uint(va[mi][0].z), __float_as_uint(va[mi][1].z),
        __float_as_uint(va[mi][0].w), __float_as_uint(va[mi][1].w),
        __float_as_uint(vb[ni].z),    __float_as_uint(vb[ni].w));
    }
}

__device__ __forceinline__ float4 tf4(float4 v){
  return make_float4(tf32_hi(v.x), tf32_hi(v.y), tf32_hi(v.z), tf32_hi(v.w));
}
__device__ __forceinline__ float4 mul4(float4 a, float4 b){
  return make_float4(a.x*b.x, a.y*b.y, a.z*b.z, a.w*b.w);
}

// ---------------- prep kernels ----------------
__global__ void k_prepW(const float* __restrict__ cqaW, const float* __restrict__ ccW){
  int tid = blockIdx.x*blockDim.x + threadIdx.x;
  int stride = gridDim.x*blockDim.x;
  for (int idx = tid; idx < 512*128; idx += stride){
    int k = idx >> 7, n = idx & 127;
    g_cqaWT[idx] = cqaW[n*512 + k];
  }
  for (int idx = tid; idx < 128*128; idx += stride){
    int k = idx >> 7, n = idx & 127;
    g_ccWT[idx] = ccW[n*256 + k];
  }
}

__global__ void __launch_bounds__(128) k_beff(const float* __restrict__ qf,
                                              const float* __restrict__ w4mlu,
                                              const float* __restrict__ w4C){
  int b = blockIdx.x, tid = threadIdx.x;
  __shared__ float s[64][129];
  for (int q0 = 0; q0 < Qn; q0 += 64){
    for (int r = 0; r < 64; r++)
      s[r][tid] = qf[((size_t)b*Qn + q0 + r)*Dn + tid];
    __syncthreads();
    for (int it = 0; it < 64; it++){
      int idx = it*128 + tid;
      int d = idx >> 6, q = idx & 63;
      g_Beff[(size_t)b*Dn*Qn + (size_t)d*Qn + q0 + q] = s[q][d]*w4mlu[d] + w4C[d];
    }
    __syncthreads();
  }
}

__global__ void __launch_bounds__(128) k_pool(const float* __restrict__ qf,
                                              const float* __restrict__ w4Q,
                                              const float* __restrict__ wp,
                                              const float* __restrict__ qmask,
                                              const float* __restrict__ ccW,
                                              const float* __restrict__ ccb){
  int b = blockIdx.x, tid = threadIdx.x;
  __shared__ float red[128];
  __shared__ float alpha[128];
  __shared__ float pooled[128];
  const float* qrow = qf + ((size_t)b*Qn + tid)*Dn;
  float bq = 0.f, lg = 0.f;
  for (int d = 0; d < Dn; d++){ float v = qrow[d]; bq += v*w4Q[d]; lg += v*wp[d]; }
  g_bq[b*Qn + tid] = bq;
  float x = lg + (1.f - qmask[b*Qn + tid])*MASK_VAL;
  red[tid] = x; __syncthreads();
  for (int s = 64; s > 0; s >>= 1){ if (tid < s) red[tid] = fmaxf(red[tid], red[tid+s]); __syncthreads(); }
  float m = red[0]; __syncthreads();
  float e = __expf(x - m);
  red[tid] = e; __syncthreads();
  for (int s = 64; s > 0; s >>= 1){ if (tid < s) red[tid] += red[tid+s]; __syncthreads(); }
  float ssum = red[0];
  alpha[tid] = e / ssum;
  __syncthreads();
  float p = 0.f;
  for (int q = 0; q < Qn; q++) p += qf[((size_t)b*Qn + q)*Dn + tid]*alpha[q];
  pooled[tid] = p; __syncthreads();
  float acc = ccb[tid];
  for (int k = 0; k < Dn; k++) acc += pooled[k]*ccW[tid*256 + 128 + k];
  g_bias2[b*Dn + tid] = acc;
}

// ---------------- score GEMM (tf32, db, swizzled) + fused softmax stats ----------------
__global__ void __launch_bounds__(256,2) k_score(const float* __restrict__ vfeats,
                                                 const float* __restrict__ vmask,
                                                 const float* __restrict__ qmask){
  int b  = blockIdx.y, bx = blockIdx.x;
  int m0 = bx*128;
  const float* A  = vfeats + (size_t)b*Cn*Dn;
  const float* Bm = g_Beff + (size_t)b*Dn*Qn;
  float* Sout = g_score + (size_t)b*Cn*Qn;
  __shared__ float As[2][128][32], Bs[2][128][32];
  __shared__ float bqs[128], qm[128], vm[128];
  __shared__ float smRm[128][2], smRs[128][2];
  __shared__ float smCm[128][4], smCs[128][4];
  int tid = threadIdx.x;
  if (tid < 128){
    bqs[tid] = g_bq[b*Qn + tid];
    qm[tid]  = (1.f - qmask[b*Qn + tid])*MASK_VAL;
    vm[tid]  = (1.f - vmask[b*Cn + m0 + tid])*MASK_VAL;
  }
  int arow = tid >> 1, aj0 = (tid & 1)*2;
  int bkl = tid >> 4, bseg = tid & 15;
  // preload chunk 0
  {
    float4 v0 = tf4(*(const float4*)&A[(size_t)(m0 + arow)*Dn + aj0*4]);
    float4 v1 = tf4(*(const float4*)&A[(size_t)(m0 + arow)*Dn + aj0*4 + 4]);
    storeA2(As[0], arow, aj0, v0, v1);
    const float* src = &Bm[(size_t)bkl*Qn + bseg*8];
    float4 w0 = *(const float4*)&src[0], w1 = *(const float4*)&src[4];
    float vv[8] = {tf32_hi(w0.x),tf32_hi(w0.y),tf32_hi(w0.z),tf32_hi(w0.w),
                   tf32_hi(w1.x),tf32_hi(w1.y),tf32_hi(w1.z),tf32_hi(w1.w)};
    storeB8(Bs[0], bseg, bkl, vv);
  }
  __syncthreads();
  int warp = tid >> 5, lane = tid & 31;
  int WM = warp >> 1, WN = warp & 1;
  int grp = lane >> 2, qd = lane & 3;
  int mb = WM*32, nb = WN*64;
  float acc[2][8][4] = {};
  for (int k0 = 0; k0 < 8; k0++){
    float4 av0, av1, bv0, bv1;
    bool nxt = (k0 < 7);
    if (nxt){
      int kn = (k0+1)*16;
      av0 = *(const float4*)&A[(size_t)(m0 + arow)*Dn + kn + aj0*4];
      av1 = *(const float4*)&A[(size_t)(m0 + arow)*Dn + kn + aj0*4 + 4];
      const float* sp = &Bm[(size_t)(kn + bkl)*Qn + bseg*8];
      bv0 = *(const float4*)&sp[0]; bv1 = *(const float4*)&sp[4];
    }
    mma_k16(As[k0&1], Bs[k0&1], acc, mb, nb, grp, qd);
    if (nxt){
      int nbuf = (k0+1)&1;
      storeA2(As[nbuf], arow, aj0, tf4(av0), tf4(av1));
      float vv[8] = {tf32_hi(bv0.x),tf32_hi(bv0.y),tf32_hi(bv0.z),tf32_hi(bv0.w),
                     tf32_hi(bv1.x),tf32_hi(bv1.y),tf32_hi(bv1.z),tf32_hi(bv1.w)};
      storeB8(Bs[nbuf], bseg, bkl, vv);
    }
    __syncthreads();
  }
  // ---- epilogue: add bq, write score, fused row/col softmax stats ----
  #pragma unroll
  for (int mi = 0; mi < 2; mi++){
    int r = m0 + mb + mi*16 + grp;
    #pragma unroll
    for (int ni = 0; ni < 8; ni++){
      int c0 = nb + ni*8 + qd*2;
      acc[mi][ni][0] += bqs[c0]; acc[mi][ni][1] += bqs[c0+1];
      acc[mi][ni][2] += bqs[c0]; acc[mi][ni][3] += bqs[c0+1];
      *(float2*)&Sout[(size_t)r*Qn + c0]     = make_float2(acc[mi][ni][0], acc[mi][ni][1]);
      *(float2*)&Sout[(size_t)(r+8)*Qn + c0] = make_float2(acc[mi][ni][2], acc[mi][ni][3]);
    }
  }
  // row stats
  #pragma unroll
  for (int s = 0; s < 4; s++){
    int mi = s >> 1, e0 = (s & 1)*2;
    float m = -INFINITY;
    #pragma unroll
    for (int ni = 0; ni < 8; ni++){
      int c0 = nb + ni*8 + qd*2;
      m = fmaxf(m, acc[mi][ni][e0]   + qm[c0]);
      m = fmaxf(m, acc[mi][ni][e0+1] + qm[c0+1]);
    }
    m = fmaxf(m, __shfl_xor_sync(0xffffffffu, m, 1));
    m = fmaxf(m, __shfl_xor_sync(0xffffffffu, m, 2));
    float ssum = 0.f;
    #pragma unroll
    for (int ni = 0; ni < 8; ni++){
      int c0 = nb + ni*8 + qd*2;
      ssum += __expf(acc[mi][ni][e0]   + qm[c0]   - m);
      ssum += __expf(acc[mi][ni][e0+1] + qm[c0+1] - m);
    }
    ssum += __shfl_xor_sync(0xffffffffu, ssum, 1);
    ssum += __shfl_xor_sync(0xffffffffu, ssum, 2);
    if (qd == 0){
      int rr = mb + mi*16 + (s & 1)*8 + grp;
      smRm[rr][WN] = m; smRs[rr][WN] = ssum;
    }
  }
  // col stats (partial over this block's 128 rows)
  float vmr[4] = { vm[mb+grp], vm[mb+grp+8], vm[mb+16+grp], vm[mb+16+grp+8] };
  #pragma unroll
  for (int g = 0; g < 4; g++){
    float cm4[4], cs4[4];
    #pragma unroll
    for (int u = 0; u < 4; u++){
      int idx = g*4 + u;
      int ni = idx >> 1, e = idx & 1;
      float m = fmaxf(fmaxf(acc[0][ni][e] + vmr[0], acc[0][ni][e+2] + vmr[1]),
                      fmaxf(acc[1][ni][e] + vmr[2], acc[1][ni][e+2] + vmr[3]));
      cm4[u] = m;
    }
    #pragma unroll
    for (int o = 4; o <= 16; o <<= 1)
      #pragma unroll
      for (int u = 0; u < 4; u++)
        cm4[u] = fmaxf(cm4[u], __shfl_xor_sync(0xffffffffu, cm4[u], o));
    #pragma unroll
    for (int u = 0; u < 4; u++){
      int idx = g*4 + u;
      int ni = idx >> 1, e = idx & 1;
      cs4[u] = __expf(acc[0][ni][e]   + vmr[0] - cm4[u])
             + __expf(acc[0][ni][e+2] + vmr[1] - cm4[u])
             + __expf(acc[1][ni][e]   + vmr[2] - cm4[u])
             + __expf(acc[1][ni][e+2] + vmr[3] - cm4[u]);
    }
    #pragma unroll
    for (int o = 4; o <= 16; o <<= 1)
      #pragma unroll
      for (int u = 0; u < 4; u++)
        cs4[u] += __shfl_xor_sync(0xffffffffu, cs4[u], o);
    if (grp == 0){
      #pragma unroll
      for (int u = 0; u < 4; u++){
        int idx = g*4 + u;
        int ni = idx >> 1, e = idx & 1;
        int col = nb + ni*8 + qd*2 + e;
        smCm[col][WM] = cm4[u]; smCs[col][WM] = cs4[u];
      }
    }
  }
  __syncthreads();
  if (tid < 128){
    float ma = smRm[tid][0], mbv = smRm[tid][1];
    float M = fmaxf(ma, mbv);
    float S = smRs[tid][0]*__expf(ma - M) + smRs[tid][1]*__expf(mbv - M);
    g_rowmax[b*Cn + m0 + tid] = M;
    g_rowsum[b*Cn + m0 + tid] = S;
    float cm2 = -INFINITY, cs2 = 0.f;
    #pragma unroll
    for (int w = 0; w < 4; w++){
      float pm = smCm[tid][w], ps = smCs[tid][w];
      float nm = fmaxf(cm2, pm);
      cs2 = cs2*__expf(cm2 - nm) + ps*__expf(pm - nm);
      cm2 = nm;
    }
    g_colpm[(b*16 + bx)*Qn + tid] = cm2;
    g_colps[(b*16 + bx)*Qn + tid] = cs2;
  }
}

__global__ void __launch_bounds__(128) k_colcombine(){
  int b = blockIdx.x, q = threadIdx.x;
  float m = -INFINITY, s = 0.f;
  for (int ch = 0; ch < 16; ch++){
    float pm = g_colpm[(b*16 + ch)*Qn + q];
    float ps = g_colps[(b*16 + ch)*Qn + q];
    float nm = fmaxf(m, pm);
    s = s*__expf(m - nm) + ps*__expf(pm - nm);
    m = nm;
  }
  g_colmax[b*Qn + q] = m;
  g_colsum[b*Qn + q] = s;
}

// ---------------- tmp = score_t^T @ V (tf32, split-K x4, db, swizzled) ----------------
__global__ void __launch_bounds__(256,2) k_tmp(const float* __restrict__ vfeats,
                                               const float* __restrict__ vmask){
  int b = blockIdx.y, ch = blockIdx.x;
  const float* Sb = g_score + (size_t)b*Cn*Qn;
  const float* V  = vfeats  + (size_t)b*Cn*Dn;
  __shared__ float As[2][128][32], Bs[2][128][32];
  __shared__ float cm[128];
  int tid = threadIdx.x;
  if (tid < 128) cm[tid] = g_colmax[b*Qn + tid];
  __syncthreads();
  int bkl = tid >> 4, bseg = tid & 15;
  int e0 = bseg*8;
  int cbase = ch*512;
  // preload chunk 0
  {
    int c = cbase + bkl;
    float mv = (1.f - vmask[b*Cn + c])*MASK_VAL;
    float4 s0 = *(const float4*)&Sb[(size_t)c*Qn + e0];
    float4 s1 = *(const float4*)&Sb[(size_t)c*Qn + e0 + 4];
    float av[8] = {tf32_hi(__expf(s0.x+mv-cm[e0+0])), tf32_hi(__expf(s0.y+mv-cm[e0+1])),
                   tf32_hi(__expf(s0.z+mv-cm[e0+2])), tf32_hi(__expf(s0.w+mv-cm[e0+3])),
                   tf32_hi(__expf(s1.x+mv-cm[e0+4])), tf32_hi(__expf(s1.y+mv-cm[e0+5])),
                   tf32_hi(__expf(s1.z+mv-cm[e0+6])), tf32_hi(__expf(s1.w+mv-cm[e0+7]))};
    storeB8(As[0], bseg, bkl, av);
    float4 v0 = *(const float4*)&V[(size_t)c*Dn + e0];
    float4 v1 = *(const float4*)&V[(size_t)c*Dn + e0 + 4];
    float bv[8] = {tf32_hi(v0.x),tf32_hi(v0.y),tf32_hi(v0.z),tf32_hi(v0.w),
                   tf32_hi(v1.x),tf32_hi(v1.y),tf32_hi(v1.z),tf32_hi(v1.w)};
    storeB8(Bs[0], bseg, bkl, bv);
  }
  __syncthreads();
  int warp = tid >> 5, lane = tid & 31;
  int WM = warp >> 1, WN = warp & 1;
  int grp = lane >> 2, qd = lane & 3;
  int mb = WM*32, nb = WN*64;
  float acc[2][8][4] = {};
  for (int kt = 0; kt < 32; kt++){
    float4 s0n, s1n, v0n, v1n; float mvn = 0.f;
    bool nxt = (kt < 31);
    if (nxt){
      int c = cbase + (kt+1)*16 + bkl;
      mvn = (1.f - vmask[b*Cn + c])*MASK_VAL;
      s0n = *(const float4*)&Sb[(size_t)c*Qn + e0];
      s1n = *(const float4*)&Sb[(size_t)c*Qn + e0 + 4];
      v0n = *(const float4*)&V[(size_t)c*Dn + e0];
      v1n = *(const float4*)&V[(size_t)c*Dn + e0 + 4];
    }
    mma_k16(As[kt&1], Bs[kt&1], acc, mb, nb, grp, qd);
    if (nxt){
      int nbuf = (kt+1)&1;
      float av[8] = {tf32_hi(__expf(s0n.x+mvn-cm[e0+0])), tf32_hi(__expf(s0n.y+mvn-cm[e0+1])),
                     tf32_hi(__expf(s0n.z+mvn-cm[e0+2])), tf32_hi(__expf(s0n.w+mvn-cm[e0+3])),
                     tf32_hi(__expf(s1n.x+mvn-cm[e0+4])), tf32_hi(__expf(s1n.y+mvn-cm[e0+5])),
                     tf32_hi(__expf(s1n.z+mvn-cm[e0+6])), tf32_hi(__expf(s1n.w+mvn-cm[e0+7]))};
      storeB8(As[nbuf], bseg, bkl, av);
      float bv[8] = {tf32_hi(v0n.x),tf32_hi(v0n.y),tf32_hi(v0n.z),tf32_hi(v0n.w),
                     tf32_hi(v1n.x),tf32_hi(v1n.y),tf32_hi(v1n.z),tf32_hi(v1n.w)};
      storeB8(Bs[nbuf], bseg, bkl, bv);
    }
    __syncthreads();
  }
  float* P = g_tmp_part + (size_t)(b*4 + ch)*Qn*Dn;
  #pragma unroll
  for (int mi = 0; mi < 2; mi++){
    int r = mb + mi*16 + grp;
    #pragma unroll
    for (int ni = 0; ni < 8; ni++){
      int col = nb + ni*8 + qd*2;
      *(float2*)&P[(size_t)r*Dn + col]     = make_float2(acc[mi][ni][0], acc[mi][ni][1]);
      *(float2*)&P[(size_t)(r+8)*Dn + col] = make_float2(acc[mi][ni][2], acc[mi][ni][3]);
    }
  }
}

__global__ void __launch_bounds__(256) k_tmp_reduce(){
  int idx = blockIdx.x*256 + threadIdx.x;
  int b = idx >> 14;
  int r = idx & 16383;
  int q = r >> 7;
  size_t base = (size_t)b*4*Qn*Dn + r;
  float s = g_tmp_part[base] + g_tmp_part[base + Qn*Dn]
          + g_tmp_part[base + 2*Qn*Dn] + g_tmp_part[base + 3*Qn*Dn];
  g_tmp[idx] = s / g_colsum[b*Qn + q];
}

// ---------------- P @ B (tf32, db, swizzled): W=0: c2q = P@qf, W=1: q2c = P@tmp ----------------
template<int W>
__global__ void __launch_bounds__(256,2) k_pgemm(const float* __restrict__ qf,
                                                 const float* __restrict__ qmask){
  int b = blockIdx.y; int m0 = blockIdx.x*128;
  const float* Sb = g_score + (size_t)b*Cn*Qn;
  const float* Bm = (W == 0 ? qf : (const float*)g_tmp) + (size_t)b*Qn*Dn;
  float* O = (W == 0 ? g_c2q : g_q2c) + ((size_t)b*Cn + m0)*Dn;
  __shared__ float As[2][128][32], Bs[2][128][32];
  __shared__ float qm[128], rm[128], ri[128];
  int tid = threadIdx.x;
  if (tid < 128){
    qm[tid] = (1.f - qmask[b*Qn + tid])*MASK_VAL;
    rm[tid] = g_rowmax[b*Cn + m0 + tid];
    ri[tid] = 1.f / g_rowsum[b*Cn + m0 + tid];
  }
  __syncthreads();
  int arow = tid >> 1, aj0 = (tid & 1)*2;
  int bkl = tid >> 4, bseg = tid & 15;
  float mm = rm[arow], rr = ri[arow];
  // preload chunk 0
  {
    int kg = aj0*4;
    float4 v = *(const float4*)&Sb[(size_t)(m0 + arow)*Qn + kg];
    float4 w = *(const float4*)&Sb[(size_t)(m0 + arow)*Qn + kg + 4];
    float4 a0 = make_float4(tf32_hi(__expf(v.x + qm[kg]   - mm)*rr),
                            tf32_hi(__expf(v.y + qm[kg+1] - mm)*rr),
                            tf32_hi(__expf(v.z + qm[kg+2] - mm)*rr),
                            tf32_hi(__expf(v.w + qm[kg+3] - mm)*rr));
    float4 a1 = make_float4(tf32_hi(__expf(w.x + qm[kg+4] - mm)*rr),
                            tf32_hi(__expf(w.y + qm[kg+5] - mm)*rr),
                            tf32_hi(__expf(w.z + qm[kg+6] - mm)*rr),
                            tf32_hi(__expf(w.w + qm[kg+7] - mm)*rr));
    storeA2(As[0], arow, aj0, a0, a1);
    const float* src = &Bm[(size_t)bkl*Dn + bseg*8];
    float4 w0 = *(const float4*)&src[0], w1 = *(const float4*)&src[4];
    float bv[8] = {tf32_hi(w0.x),tf32_hi(w0.y),tf32_hi(w0.z),tf32_hi(w0.w),
                   tf32_hi(w1.x),tf32_hi(w1.y),tf32_hi(w1.z),tf32_hi(w1.w)};
    storeB8(Bs[0], bseg, bkl, bv);
  }
  __syncthreads();
  int warp = tid >> 5, lane = tid & 31;
  int WM = warp >> 1, WN = warp & 1;
  int grp = lane >> 2, qd = lane & 3;
  int mb = WM*32, nb = WN*64;
  float acc[2][8][4] = {};
  for (int k0 = 0; k0 < 8; k0++){
    float4 av0, av1, bv0, bv1;
    bool nxt = (k0 < 7);
    if (nxt){
      int kn = (k0+1)*16;
      av0 = *(const float4*)&Sb[(size_t)(m0 + arow)*Qn + kn + aj0*4];
      av1 = *(const float4*)&Sb[(size_t)(m0 + arow)*Qn + kn + aj0*4 + 4];
      const float* sp = &Bm[(size_t)(kn + bkl)*Dn + bseg*8];
      bv0 = *(const float4*)&sp[0]; bv1 = *(const float4*)&sp[4];
    }
    mma_k16(As[k0&1], Bs[k0&1], acc, mb, nb, grp, qd);
    if (nxt){
      int nbuf = (k0+1)&1;
      int kg = (k0+1)*16 + aj0*4;
      float4 a0 = make_float4(tf32_hi(__expf(av0.x + qm[kg]   - mm)*rr),
                              tf32_hi(__expf(av0.y + qm[kg+1] - mm)*rr),
                              tf32_hi(__expf(av0.z + qm[kg+2] - mm)*rr),
                              tf32_hi(__expf(av0.w + qm[kg+3] - mm)*rr));
      float4 a1 = make_float4(tf32_hi(__expf(av1.x + qm[kg+4] - mm)*rr),
                              tf32_hi(__expf(av1.y + qm[kg+5] - mm)*rr),
                              tf32_hi(__expf(av1.z + qm[kg+6] - mm)*rr),
                              tf32_hi(__expf(av1.w + qm[kg+7] - mm)*rr));
      storeA2(As[nbuf], arow, aj0, a0, a1);
      float bv[8] = {tf32_hi(bv0.x),tf32_hi(bv0.y),tf32_hi(bv0.z),tf32_hi(bv0.w),
                     tf32_hi(bv1.x),tf32_hi(bv1.y),tf32_hi(bv1.z),tf32_hi(bv1.w)};
      storeB8(Bs[nbuf], bseg, bkl, bv);
    }
    __syncthreads();
  }
  #pragma unroll
  for (int mi = 0; mi < 2; mi++){
    int r = mb + mi*16 + grp;
    #pragma unroll
    for (int ni = 0; ni < 8; ni++){
      int col = nb + ni*8 + qd*2;
      *(float2*)&O[(size_t)r*Dn + col]     = make_float2(acc[mi][ni][0], acc[mi][ni][1]);
      *(float2*)&O[(size_t)(r+8)*Dn + col] = make_float2(acc[mi][ni][2], acc[mi][ni][3]);
    }
  }
}

// ---------------- feats = [v, c2q, v*c2q, v*q2c] @ cqa_W^T + b ----------------
// Source-grouped k-order: it -> (g = it>>2 k-column group, s = it&3 source).
// v and c2q chunks for each group are loaded ONCE and kept in registers;
// src2 (v*c2q) needs no global load, src3 reuses the v registers.
__global__ void __launch_bounds__(256,2) k_feats(const float* __restrict__ vfeats,
                                                 const float* __restrict__ cqa_b){
  size_t m0 = (size_t)blockIdx.x*128;
  __shared__ float As[2][128][32], Bs[2][128][32];
  __shared__ float cb[128];
  int tid = threadIdx.x;
  if (tid < 128) cb[tid] = cqa_b[tid];
  int arow = tid >> 1, aj0 = (tid & 1)*2;
  int bkl = tid >> 4, bseg = tid & 15;
  float4 vk0, vk1, ck0, ck1;  // persistent v / c2q chunk registers
  // preload it=0: g=0, s=0 -> vfeats chunk 0
  {
    size_t off0 = (m0 + arow)*(size_t)Dn + aj0*4;
    vk0 = *(const float4*)&vfeats[off0];
    vk1 = *(const float4*)&vfeats[off0+4];
    storeA2(As[0], arow, aj0, tf4(vk0), tf4(vk1));
    const float* srcp = &g_cqaWT[bkl*128 + bseg*8];  // B row s*128+g*16 = 0
    float4 w0 = *(const float4*)&srcp[0], w1 = *(const float4*)&srcp[4];
    float bv[8] = {tf32_hi(w0.x),tf32_hi(w0.y),tf32_hi(w0.z),tf32_hi(w0.w),
                   tf32_hi(w1.x),tf32_hi(w1.y),tf32_hi(w1.z),tf32_hi(w1.w)};
    storeB8(Bs[0], bseg, bkl, bv);
  }
  __syncthreads();
  int warp = tid >> 5, lane = tid & 31;
  int WM = warp >> 1, WN = warp & 1;
  int grp = lane >> 2, qd = lane & 3;
  int mb = WM*32, nb = WN*64;
  float acc[2][8][4] = {};
  #pragma unroll 4
  for (int it = 0; it < 32; it++){
    float4 av0, av1, bv0, bv1;
    int it2 = it + 1, g2 = it2 >> 2, s2 = it2 & 3;
    bool nxt = (it < 31);
    if (nxt){
      size_t off0 = (m0 + arow)*(size_t)Dn + g2*16 + aj0*4;
      if (s2 == 0)      { av0 = *(const float4*)&vfeats[off0]; av1 = *(const float4*)&vfeats[off0+4]; }
      else if (s2 == 1) { av0 = *(const float4*)&g_c2q[off0];  av1 = *(const float4*)&g_c2q[off0+4]; }
      else if (s2 == 3) { av0 = *(const float4*)&g_q2c[off0];  av1 = *(const float4*)&g_q2c[off0+4]; }
      // s2 == 2: no global load (v*c2q from registers)
      const float* sp = &g_cqaWT[(s2*128 + g2*16 + bkl)*128 + bseg*8];
      bv0 = *(const float4*)&sp[0]; bv1 = *(const float4*)&sp[4];
    }
    mma_k16(As[it&1], Bs[it&1], acc, mb, nb, grp, qd);
    if (nxt){
      int nbuf = it2 & 1;
      float4 a0, a1;
      if (s2 == 0)      { vk0 = av0; vk1 = av1; a0 = av0; a1 = av1; }
      else if (s2 == 1) { ck0 = av0; ck1 = av1; a0 = av0; a1 = av1; }
      else if (s2 == 2) { a0 = mul4(vk0, ck0); a1 = mul4(vk1, ck1); }
      else              { a0 = mul4(vk0, av0); a1 = mul4(vk1, av1); }
      storeA2(As[nbuf], arow, aj0, tf4(a0), tf4(a1));
      float bv[8] = {tf32_hi(bv0.x),tf32_hi(bv0.y),tf32_hi(bv0.z),tf32_hi(bv0.w),
                     tf32_hi(bv1.x),tf32_hi(bv1.y),tf32_hi(bv1.z),tf32_hi(bv1.w)};
      storeB8(Bs[nbuf], bseg, bkl, bv);
    }
    __syncthreads();
  }
  #pragma unroll
  for (int mi = 0; mi < 2; mi++){
    size_t r = m0 + mb + mi*16 + grp;
    #pragma unroll
    for (int ni = 0; ni < 8; ni++){
      int col = nb + ni*8 + qd*2;
      *(float2*)&g_feats[r*Dn + col]     = make_float2(acc[mi][ni][0] + cb[col], acc[mi][ni][1] + cb[col+1]);
      *(float2*)&g_feats[(r+8)*Dn + col] = make_float2(acc[mi][ni][2] + cb[col], acc[mi][ni][3] + cb[col+1]);
    }
  }
}

// ---------------- out = relu(feats @ ccW1^T + bias2[b]) (tf32, db, swizzled) ----------------
__global__ void __launch_bounds__(256,2) k_out(float* __restrict__ out){
  size_t m0 = (size_t)blockIdx.x*128;
  int bb = (int)(m0 >> 11);
  __shared__ float As[2][128][32], Bs[2][128][32];
  __shared__ float b2s[128];
  int tid = threadIdx.x;
  if (tid < 128) b2s[tid] = g_bias2[bb*Dn + tid];
  int arow = tid >> 1, aj0 = (tid & 1)*2;
  int bkl = tid >> 4, bseg = tid & 15;
  // preload chunk 0
  {
    float4 v0 = tf4(*(const float4*)&g_feats[(m0 + arow)*(size_t)Dn + aj0*4]);
    float4 v1 = tf4(*(const float4*)&g_feats[(m0 + arow)*(size_t)Dn + aj0*4 + 4]);
    storeA2(As[0], arow, aj0, v0, v1);
    const float* src = &g_ccWT[bkl*128 + bseg*8];
    float4 w0 = *(const float4*)&src[0], w1 = *(const float4*)&src[4];
    float bv[8] = {tf32_hi(w0.x),tf32_hi(w0.y),tf32_hi(w0.z),tf32_hi(w0.w),
                   tf32_hi(w1.x),tf32_hi(w1.y),tf32_hi(w1.z),tf32_hi(w1.w)};
    storeB8(Bs[0], bseg, bkl, bv);
  }
  __syncthreads();
  int warp = tid >> 5, lane = tid & 31;
  int WM = warp >> 1, WN = warp & 1;
  int grp = lane >> 2, qd = lane & 3;
  int mb = WM*32, nb = WN*64;
  float acc[2][8][4] = {};
  for (int k0 = 0; k0 < 8; k0++){
    float4 av0, av1, bv0, bv1;
    bool nxt = (k0 < 7);
    if (nxt){
      int kn = (k0+1)*16;
      av0 = *(const float4*)&g_feats[(m0 + arow)*(size_t)Dn + kn + aj0*4];
      av1 = *(const float4*)&g_feats[(m0 + arow)*(size_t)Dn + kn + aj0*4 + 4];
      const float* sp = &g_ccWT[(kn + bkl)*128 + bseg*8];
      bv0 = *(const float4*)&sp[0]; bv1 = *(const float4*)&sp[4];
    }
    mma_k16(As[k0&1], Bs[k0&1], acc, mb, nb, grp, qd);
    if (nxt){
      int nbuf = (k0+1)&1;
      storeA2(As[nbuf], arow, aj0, tf4(av0), tf4(av1));
      float bv[8] = {tf32_hi(bv0.x),tf32_hi(bv0.y),tf32_hi(bv0.z),tf32_hi(bv0.w),
                     tf32_hi(bv1.x),tf32_hi(bv1.y),tf32_hi(bv1.z),tf32_hi(bv1.w)};
      storeB8(Bs[nbuf], bseg, bkl, bv);
    }
    __syncthreads();
  }
  #pragma unroll
  for (int mi = 0; mi < 2; mi++){
    size_t r = m0 + mb + mi*16 + grp;
    #pragma unroll
    for (int ni = 0; ni < 8; ni++){
      int col = nb + ni*8 + qd*2;
      float2 w0 = make_float2(fmaxf(acc[mi][ni][0] + b2s[col], 0.f), fmaxf(acc[mi][ni][1] + b2s[col+1], 0.f));
      float2 w1 = make_float2(fmaxf(acc[mi][ni][2] + b2s[col], 0.f), fmaxf(acc[mi][ni][3] + b2s[col+1], 0.f));
      *(float2*)&out[r*Dn + col]     = w0;
      *(float2*)&out[(r+8)*Dn + col] = w1;
    }
  }
}

// ---------------- launch ----------------
extern "C" void kernel_launch(void* const* d_in, const int* in_sizes, int n_in,
                              void* d_out, int out_size){
  const float* vfeats = (const float*)d_in[0];
  const float* qfeats = (const float*)d_in[1];
  const float* vmask  = (const float*)d_in[2];
  const float* qmask  = (const float*)d_in[3];
  const float* w4C    = (const float*)d_in[4];
  const float* w4Q    = (const float*)d_in[5];
  const float* w4mlu  = (const float*)d_in[6];
  const float* cqa_W  = (const float*)d_in[7];
  const float* cqa_b  = (const float*)d_in[8];
  const float* wp     = (const float*)d_in[9];
  const float* cc_W   = (const float*)d_in[10];
  const float* cc_b   = (const float*)d_in[11];
  float* out = (float*)d_out;

  k_prepW<<<128, 256>>>(cqa_W, cc_W);
  k_beff<<<Bn, 128>>>(qfeats, w4mlu, w4C);
  k_pool<<<Bn, 128>>>(qfeats, w4Q, wp, qmask, cc_W, cc_b);
  k_score<<<dim3(Cn/128, Bn), 256>>>(vfeats, vmask, qmask);
  k_colcombine<<<Bn, 128>>>();
  k_tmp<<<dim3(4, Bn), 256>>>(vfeats, vmask);
  k_tmp_reduce<<<(Bn*Qn*Dn)/256, 256>>>();
  k_pgemm<0><<<dim3(Cn/128, Bn), 256>>>(qfeats, qmask);
  k_pgemm<1><<<dim3(Cn/128, Bn), 256>>>(qfeats, qmask);
  k_feats<<<(Bn*Cn)/128, 256>>>(vfeats, cqa_b);
  k_out<<<(Bn*Cn)/128, 256>>>(out);
}

// round 14
// speedup vs baseline: 1.5163x; 1.5163x over previous
#include <cuda_runtime.h>
#include <math.h>

#define Bn 64
#define Cn 2048
#define Qn 128
#define Dn 128
#define MASK_VAL (-1e30f)

// ---------------- scratch ----------------
__device__ float g_score[(size_t)Bn*Cn*Qn];
__device__ float g_Beff [(size_t)Bn*Dn*Qn];
__device__ float g_bq   [Bn*Qn];
__device__ float g_rowmax[Bn*Cn];
__device__ float g_rowsum[Bn*Cn];
__device__ float g_colpm[Bn*16*Qn];
__device__ float g_colps[Bn*16*Qn];
__device__ float g_colmax[Bn*Qn];
__device__ float g_colsum[Bn*Qn];
__device__ float g_tmp_part[(size_t)Bn*4*Qn*Dn];
__device__ float g_tmp [(size_t)Bn*Qn*Dn];
__device__ float g_bias2[Bn*Dn];
__device__ float g_c2q [(size_t)Bn*Cn*Dn];
__device__ float g_q2c [(size_t)Bn*Cn*Dn];
__device__ float g_feats[(size_t)Bn*Cn*Dn];
__device__ float g_cqaWT[512*128];
__device__ float g_ccWT [128*128];

// ---------------- tf32 helpers ----------------
__device__ __forceinline__ unsigned cvt_tf32(float x){
  unsigned u; asm("cvt.rna.tf32.f32 %0, %1;" : "=r"(u) : "f"(x)); return u;
}
__device__ __forceinline__ float tf32_hi(float x){ return __uint_as_float(cvt_tf32(x)); }

#define MMA_TF32(D, A0,A1,A2,A3, B0,B1) \
  asm volatile("mma.sync.aligned.m16n8k8.row.col.f32.tf32.tf32.f32 " \
      "{%0,%1,%2,%3}, {%4,%5,%6,%7}, {%8,%9}, {%0,%1,%2,%3};" \
      : "+f"(D[0]), "+f"(D[1]), "+f"(D[2]), "+f"(D[3]) \
      : "r"(A0), "r"(A1), "r"(A2), "r"(A3), "r"(B0), "r"(B1))

// ---- swizzled fragment tile [rows][32]:
// element k (0..15) of row n stored at quad ((k&3) + (n&7) + (n>>3)) & 7, offset k>>2.

__device__ __forceinline__ void storeB8(float (*T)[32], int bseg, int bkl, const float* v8){
  int bq = bkl >> 2, bc = bkl & 3;
  int e0 = bseg*8;
  #pragma unroll
  for (int e = 0; e < 8; e++)
    T[e0+e][((bc + e + bseg) & 7)*4 + bq] = v8[e];
}
__device__ __forceinline__ void storeA2(float (*T)[32], int arow, int aj0,
                                        const float4& v0, const float4& v1){
  int ga = (arow & 7) + (arow >> 3);
  const float* p0 = (const float*)&v0;
  const float* p1 = (const float*)&v1;
  #pragma unroll
  for (int t = 0; t < 4; t++){
    T[arow][((t + ga) & 7)*4 + aj0]     = p0[t];
    T[arow][((t + ga) & 7)*4 + aj0 + 1] = p1[t];
  }
}

// Per-warp 32x64 tile MMA over a k16 chunk, swizzled tiles.
__device__ __forceinline__ void mma_k16(const float (*As)[32], const float (*Bs)[32],
                                        float acc[2][8][4], int mb, int nb, int grp, int qd){
  int baseq = qd + grp;
  int mh = mb >> 3, nh = nb >> 3;
  float4 va[2][2];
  #pragma unroll
  for (int mi = 0; mi < 2; mi++){
    int r = mb + mi*16 + grp;
    va[mi][0] = *(const float4*)&As[r][((baseq + mh + mi*2) & 7)*4];
    va[mi][1] = *(const float4*)&As[r+8][((baseq + mh + mi*2 + 1) & 7)*4];
  }
  float4 vb[8];
  #pragma unroll
  for (int ni = 0; ni < 8; ni++){
    int n = nb + ni*8 + grp;
    vb[ni] = *(const float4*)&Bs[n][((baseq + nh + ni) & 7)*4];
  }
  #pragma unroll
  for (int mi = 0; mi < 2; mi++)
    #pragma unroll
    for (int ni = 0; ni < 8; ni++){
      MMA_TF32(acc[mi][ni],
        __float_as_uint(va[mi][0].x), __float_as_uint(va[mi][1].x),
        __float_as_uint(va[mi][0].y), __float_as_uint(va[mi][1].y),
        __float_as_uint(vb[ni].x),    __float_as_uint(vb[ni].y));
      MMA_TF32(acc[mi][ni],
        __float_as_uint(va[mi][0].z), __float_as_uint(va[mi][1].z),
        __float_as_uint(va[mi][0].w), __float_as_uint(va[mi][1].w),
        __float_as_uint(vb[ni].z),    __float_as_uint(vb[ni].w));
    }
}

__device__ __forceinline__ float4 tf4(float4 v){
  return make_float4(tf32_hi(v.x), tf32_hi(v.y), tf32_hi(v.z), tf32_hi(v.w));
}
__device__ __forceinline__ float4 mul4(float4 a, float4 b){
  return make_float4(a.x*b.x, a.y*b.y, a.z*b.z, a.w*b.w);
}

// ---------------- prep kernels ----------------
__global__ void k_prepW(const float* __restrict__ cqaW, const float* __restrict__ ccW){
  int tid = blockIdx.x*blockDim.x + threadIdx.x;
  int stride = gridDim.x*blockDim.x;
  for (int idx = tid; idx < 512*128; idx += stride){
    int k = idx >> 7, n = idx & 127;
    g_cqaWT[idx] = cqaW[n*512 + k];
  }
  for (int idx = tid; idx < 128*128; idx += stride){
    int k = idx >> 7, n = idx & 127;
    g_ccWT[idx] = ccW[n*256 + k];
  }
}

__global__ void __launch_bounds__(128) k_beff(const float* __restrict__ qf,
                                              const float* __restrict__ w4mlu,
                                              const float* __restrict__ w4C){
  int b = blockIdx.x, tid = threadIdx.x;
  __shared__ float s[64][129];
  for (int q0 = 0; q0 < Qn; q0 += 64){
    for (int r = 0; r < 64; r++)
      s[r][tid] = qf[((size_t)b*Qn + q0 + r)*Dn + tid];
    __syncthreads();
    for (int it = 0; it < 64; it++){
      int idx = it*128 + tid;
      int d = idx >> 6, q = idx & 63;
      g_Beff[(size_t)b*Dn*Qn + (size_t)d*Qn + q0 + q] = s[q][d]*w4mlu[d] + w4C[d];
    }
    __syncthreads();
  }
}

__global__ void __launch_bounds__(128) k_pool(const float* __restrict__ qf,
                                              const float* __restrict__ w4Q,
                                              const float* __restrict__ wp,
                                              const float* __restrict__ qmask,
                                              const float* __restrict__ ccW,
                                              const float* __restrict__ ccb){
  int b = blockIdx.x, tid = threadIdx.x;
  __shared__ float red[128];
  __shared__ float alpha[128];
  __shared__ float pooled[128];
  const float* qrow = qf + ((size_t)b*Qn + tid)*Dn;
  float bq = 0.f, lg = 0.f;
  for (int d = 0; d < Dn; d++){ float v = qrow[d]; bq += v*w4Q[d]; lg += v*wp[d]; }
  g_bq[b*Qn + tid] = bq;
  float x = lg + (1.f - qmask[b*Qn + tid])*MASK_VAL;
  red[tid] = x; __syncthreads();
  for (int s = 64; s > 0; s >>= 1){ if (tid < s) red[tid] = fmaxf(red[tid], red[tid+s]); __syncthreads(); }
  float m = red[0]; __syncthreads();
  float e = __expf(x - m);
  red[tid] = e; __syncthreads();
  for (int s = 64; s > 0; s >>= 1){ if (tid < s) red[tid] += red[tid+s]; __syncthreads(); }
  float ssum = red[0];
  alpha[tid] = e / ssum;
  __syncthreads();
  float p = 0.f;
  for (int q = 0; q < Qn; q++) p += qf[((size_t)b*Qn + q)*Dn + tid]*alpha[q];
  pooled[tid] = p; __syncthreads();
  float acc = ccb[tid];
  for (int k = 0; k < Dn; k++) acc += pooled[k]*ccW[tid*256 + 128 + k];
  g_bias2[b*Dn + tid] = acc;
}

// ---------------- score GEMM (tf32, db, swizzled) + fused softmax stats ----------------
__global__ void __launch_bounds__(256,2) k_score(const float* __restrict__ vfeats,
                                                 const float* __restrict__ vmask,
                                                 const float* __restrict__ qmask){
  int b  = blockIdx.y, bx = blockIdx.x;
  int m0 = bx*128;
  const float* A  = vfeats + (size_t)b*Cn*Dn;
  const float* Bm = g_Beff + (size_t)b*Dn*Qn;
  float* Sout = g_score + (size_t)b*Cn*Qn;
  __shared__ float As[2][128][32], Bs[2][128][32];
  __shared__ float bqs[128], qm[128], vm[128];
  __shared__ float smRm[128][2], smRs[128][2];
  __shared__ float smCm[128][4], smCs[128][4];
  int tid = threadIdx.x;
  if (tid < 128){
    bqs[tid] = g_bq[b*Qn + tid];
    qm[tid]  = (1.f - qmask[b*Qn + tid])*MASK_VAL;
    vm[tid]  = (1.f - vmask[b*Cn + m0 + tid])*MASK_VAL;
  }
  int arow = tid >> 1, aj0 = (tid & 1)*2;
  int bkl = tid >> 4, bseg = tid & 15;
  // preload chunk 0
  {
    float4 v0 = tf4(*(const float4*)&A[(size_t)(m0 + arow)*Dn + aj0*4]);
    float4 v1 = tf4(*(const float4*)&A[(size_t)(m0 + arow)*Dn + aj0*4 + 4]);
    storeA2(As[0], arow, aj0, v0, v1);
    const float* src = &Bm[(size_t)bkl*Qn + bseg*8];
    float4 w0 = *(const float4*)&src[0], w1 = *(const float4*)&src[4];
    float vv[8] = {tf32_hi(w0.x),tf32_hi(w0.y),tf32_hi(w0.z),tf32_hi(w0.w),
                   tf32_hi(w1.x),tf32_hi(w1.y),tf32_hi(w1.z),tf32_hi(w1.w)};
    storeB8(Bs[0], bseg, bkl, vv);
  }
  __syncthreads();
  int warp = tid >> 5, lane = tid & 31;
  int WM = warp >> 1, WN = warp & 1;
  int grp = lane >> 2, qd = lane & 3;
  int mb = WM*32, nb = WN*64;
  float acc[2][8][4] = {};
  for (int k0 = 0; k0 < 8; k0++){
    float4 av0, av1, bv0, bv1;
    bool nxt = (k0 < 7);
    if (nxt){
      int kn = (k0+1)*16;
      av0 = *(const float4*)&A[(size_t)(m0 + arow)*Dn + kn + aj0*4];
      av1 = *(const float4*)&A[(size_t)(m0 + arow)*Dn + kn + aj0*4 + 4];
      const float* sp = &Bm[(size_t)(kn + bkl)*Qn + bseg*8];
      bv0 = *(const float4*)&sp[0]; bv1 = *(const float4*)&sp[4];
    }
    mma_k16(As[k0&1], Bs[k0&1], acc, mb, nb, grp, qd);
    if (nxt){
      int nbuf = (k0+1)&1;
      storeA2(As[nbuf], arow, aj0, tf4(av0), tf4(av1));
      float vv[8] = {tf32_hi(bv0.x),tf32_hi(bv0.y),tf32_hi(bv0.z),tf32_hi(bv0.w),
                     tf32_hi(bv1.x),tf32_hi(bv1.y),tf32_hi(bv1.z),tf32_hi(bv1.w)};
      storeB8(Bs[nbuf], bseg, bkl, vv);
    }
    __syncthreads();
  }
  // ---- epilogue: add bq, write score, fused row/col softmax stats ----
  #pragma unroll
  for (int mi = 0; mi < 2; mi++){
    int r = m0 + mb + mi*16 + grp;
    #pragma unroll
    for (int ni = 0; ni < 8; ni++){
      int c0 = nb + ni*8 + qd*2;
      acc[mi][ni][0] += bqs[c0]; acc[mi][ni][1] += bqs[c0+1];
      acc[mi][ni][2] += bqs[c0]; acc[mi][ni][3] += bqs[c0+1];
      *(float2*)&Sout[(size_t)r*Qn + c0]     = make_float2(acc[mi][ni][0], acc[mi][ni][1]);
      *(float2*)&Sout[(size_t)(r+8)*Qn + c0] = make_float2(acc[mi][ni][2], acc[mi][ni][3]);
    }
  }
  // row stats
  #pragma unroll
  for (int s = 0; s < 4; s++){
    int mi = s >> 1, e0 = (s & 1)*2;
    float m = -INFINITY;
    #pragma unroll
    for (int ni = 0; ni < 8; ni++){
      int c0 = nb + ni*8 + qd*2;
      m = fmaxf(m, acc[mi][ni][e0]   + qm[c0]);
      m = fmaxf(m, acc[mi][ni][e0+1] + qm[c0+1]);
    }
    m = fmaxf(m, __shfl_xor_sync(0xffffffffu, m, 1));
    m = fmaxf(m, __shfl_xor_sync(0xffffffffu, m, 2));
    float ssum = 0.f;
    #pragma unroll
    for (int ni = 0; ni < 8; ni++){
      int c0 = nb + ni*8 + qd*2;
      ssum += __expf(acc[mi][ni][e0]   + qm[c0]   - m);
      ssum += __expf(acc[mi][ni][e0+1] + qm[c0+1] - m);
    }
    ssum += __shfl_xor_sync(0xffffffffu, ssum, 1);
    ssum += __shfl_xor_sync(0xffffffffu, ssum, 2);
    if (qd == 0){
      int rr = mb + mi*16 + (s & 1)*8 + grp;
      smRm[rr][WN] = m; smRs[rr][WN] = ssum;
    }
  }
  // col stats (partial over this block's 128 rows)
  float vmr[4] = { vm[mb+grp], vm[mb+grp+8], vm[mb+16+grp], vm[mb+16+grp+8] };
  #pragma unroll
  for (int g = 0; g < 4; g++){
    float cm4[4], cs4[4];
    #pragma unroll
    for (int u = 0; u < 4; u++){
      int idx = g*4 + u;
      int ni = idx >> 1, e = idx & 1;
      float m = fmaxf(fmaxf(acc[0][ni][e] + vmr[0], acc[0][ni][e+2] + vmr[1]),
                      fmaxf(acc[1][ni][e] + vmr[2], acc[1][ni][e+2] + vmr[3]));
      cm4[u] = m;
    }
    #pragma unroll
    for (int o = 4; o <= 16; o <<= 1)
      #pragma unroll
      for (int u = 0; u < 4; u++)
        cm4[u] = fmaxf(cm4[u], __shfl_xor_sync(0xffffffffu, cm4[u], o));
    #pragma unroll
    for (int u = 0; u < 4; u++){
      int idx = g*4 + u;
      int ni = idx >> 1, e = idx & 1;
      cs4[u] = __expf(acc[0][ni][e]   + vmr[0] - cm4[u])
             + __expf(acc[0][ni][e+2] + vmr[1] - cm4[u])
             + __expf(acc[1][ni][e]   + vmr[2] - cm4[u])
             + __expf(acc[1][ni][e+2] + vmr[3] - cm4[u]);
    }
    #pragma unroll
    for (int o = 4; o <= 16; o <<= 1)
      #pragma unroll
      for (int u = 0; u < 4; u++)
        cs4[u] += __shfl_xor_sync(0xffffffffu, cs4[u], o);
    if (grp == 0){
      #pragma unroll
      for (int u = 0; u < 4; u++){
        int idx = g*4 + u;
        int ni = idx >> 1, e = idx & 1;
        int col = nb + ni*8 + qd*2 + e;
        smCm[col][WM] = cm4[u]; smCs[col][WM] = cs4[u];
      }
    }
  }
  __syncthreads();
  if (tid < 128){
    float ma = smRm[tid][0], mbv = smRm[tid][1];
    float M = fmaxf(ma, mbv);
    float S = smRs[tid][0]*__expf(ma - M) + smRs[tid][1]*__expf(mbv - M);
    g_rowmax[b*Cn + m0 + tid] = M;
    g_rowsum[b*Cn + m0 + tid] = S;
    float cm2 = -INFINITY, cs2 = 0.f;
    #pragma unroll
    for (int w = 0; w < 4; w++){
      float pm = smCm[tid][w], ps = smCs[tid][w];
      float nm = fmaxf(cm2, pm);
      cs2 = cs2*__expf(cm2 - nm) + ps*__expf(pm - nm);
      cm2 = nm;
    }
    g_colpm[(b*16 + bx)*Qn + tid] = cm2;
    g_colps[(b*16 + bx)*Qn + tid] = cs2;
  }
}

__global__ void __launch_bounds__(128) k_colcombine(){
  int b = blockIdx.x, q = threadIdx.x;
  float m = -INFINITY, s = 0.f;
  for (int ch = 0; ch < 16; ch++){
    float pm = g_colpm[(b*16 + ch)*Qn + q];
    float ps = g_colps[(b*16 + ch)*Qn + q];
    float nm = fmaxf(m, pm);
    s = s*__expf(m - nm) + ps*__expf(pm - nm);
    m = nm;
  }
  g_colmax[b*Qn + q] = m;
  g_colsum[b*Qn + q] = s;
}

// ---------------- tmp = score_t^T @ V (tf32, split-K x4, db, swizzled) ----------------
__global__ void __launch_bounds__(256,2) k_tmp(const float* __restrict__ vfeats,
                                               const float* __restrict__ vmask){
  int b = blockIdx.y, ch = blockIdx.x;
  const float* Sb = g_score + (size_t)b*Cn*Qn;
  const float* V  = vfeats  + (size_t)b*Cn*Dn;
  __shared__ float As[2][128][32], Bs[2][128][32];
  __shared__ float cm[128];
  int tid = threadIdx.x;
  if (tid < 128) cm[tid] = g_colmax[b*Qn + tid];
  __syncthreads();
  int bkl = tid >> 4, bseg = tid & 15;
  int e0 = bseg*8;
  int cbase = ch*512;
  // preload chunk 0
  {
    int c = cbase + bkl;
    float mv = (1.f - vmask[b*Cn + c])*MASK_VAL;
    float4 s0 = *(const float4*)&Sb[(size_t)c*Qn + e0];
    float4 s1 = *(const float4*)&Sb[(size_t)c*Qn + e0 + 4];
    float av[8] = {tf32_hi(__expf(s0.x+mv-cm[e0+0])), tf32_hi(__expf(s0.y+mv-cm[e0+1])),
                   tf32_hi(__expf(s0.z+mv-cm[e0+2])), tf32_hi(__expf(s0.w+mv-cm[e0+3])),
                   tf32_hi(__expf(s1.x+mv-cm[e0+4])), tf32_hi(__expf(s1.y+mv-cm[e0+5])),
                   tf32_hi(__expf(s1.z+mv-cm[e0+6])), tf32_hi(__expf(s1.w+mv-cm[e0+7]))};
    storeB8(As[0], bseg, bkl, av);
    float4 v0 = *(const float4*)&V[(size_t)c*Dn + e0];
    float4 v1 = *(const float4*)&V[(size_t)c*Dn + e0 + 4];
    float bv[8] = {tf32_hi(v0.x),tf32_hi(v0.y),tf32_hi(v0.z),tf32_hi(v0.w),
                   tf32_hi(v1.x),tf32_hi(v1.y),tf32_hi(v1.z),tf32_hi(v1.w)};
    storeB8(Bs[0], bseg, bkl, bv);
  }
  __syncthreads();
  int warp = tid >> 5, lane = tid & 31;
  int WM = warp >> 1, WN = warp & 1;
  int grp = lane >> 2, qd = lane & 3;
  int mb = WM*32, nb = WN*64;
  float acc[2][8][4] = {};
  for (int kt = 0; kt < 32; kt++){
    float4 s0n, s1n, v0n, v1n; float mvn = 0.f;
    bool nxt = (kt < 31);
    if (nxt){
      int c = cbase + (kt+1)*16 + bkl;
      mvn = (1.f - vmask[b*Cn + c])*MASK_VAL;
      s0n = *(const float4*)&Sb[(size_t)c*Qn + e0];
      s1n = *(const float4*)&Sb[(size_t)c*Qn + e0 + 4];
      v0n = *(const float4*)&V[(size_t)c*Dn + e0];
      v1n = *(const float4*)&V[(size_t)c*Dn + e0 + 4];
    }
    mma_k16(As[kt&1], Bs[kt&1], acc, mb, nb, grp, qd);
    if (nxt){
      int nbuf = (kt+1)&1;
      float av[8] = {tf32_hi(__expf(s0n.x+mvn-cm[e0+0])), tf32_hi(__expf(s0n.y+mvn-cm[e0+1])),
                     tf32_hi(__expf(s0n.z+mvn-cm[e0+2])), tf32_hi(__expf(s0n.w+mvn-cm[e0+3])),
                     tf32_hi(__expf(s1n.x+mvn-cm[e0+4])), tf32_hi(__expf(s1n.y+mvn-cm[e0+5])),
                     tf32_hi(__expf(s1n.z+mvn-cm[e0+6])), tf32_hi(__expf(s1n.w+mvn-cm[e0+7]))};
      storeB8(As[nbuf], bseg, bkl, av);
      float bv[8] = {tf32_hi(v0n.x),tf32_hi(v0n.y),tf32_hi(v0n.z),tf32_hi(v0n.w),
                     tf32_hi(v1n.x),tf32_hi(v1n.y),tf32_hi(v1n.z),tf32_hi(v1n.w)};
      storeB8(Bs[nbuf], bseg, bkl, bv);
    }
    __syncthreads();
  }
  float* P = g_tmp_part + (size_t)(b*4 + ch)*Qn*Dn;
  #pragma unroll
  for (int mi = 0; mi < 2; mi++){
    int r = mb + mi*16 + grp;
    #pragma unroll
    for (int ni = 0; ni < 8; ni++){
      int col = nb + ni*8 + qd*2;
      *(float2*)&P[(size_t)r*Dn + col]     = make_float2(acc[mi][ni][0], acc[mi][ni][1]);
      *(float2*)&P[(size_t)(r+8)*Dn + col] = make_float2(acc[mi][ni][2], acc[mi][ni][3]);
    }
  }
}

__global__ void __launch_bounds__(256) k_tmp_reduce(){
  int idx = blockIdx.x*256 + threadIdx.x;
  int b = idx >> 14;
  int r = idx & 16383;
  int q = r >> 7;
  size_t base = (size_t)b*4*Qn*Dn + r;
  float s = g_tmp_part[base] + g_tmp_part[base + Qn*Dn]
          + g_tmp_part[base + 2*Qn*Dn] + g_tmp_part[base + 3*Qn*Dn];
  g_tmp[idx] = s / g_colsum[b*Qn + q];
}

// ---------------- P @ B (tf32, db, swizzled): W=0: c2q = P@qf, W=1: q2c = P@tmp ----------------
template<int W>
__global__ void __launch_bounds__(256,2) k_pgemm(const float* __restrict__ qf,
                                                 const float* __restrict__ qmask){
  int b = blockIdx.y; int m0 = blockIdx.x*128;
  const float* Sb = g_score + (size_t)b*Cn*Qn;
  const float* Bm = (W == 0 ? qf : (const float*)g_tmp) + (size_t)b*Qn*Dn;
  float* O = (W == 0 ? g_c2q : g_q2c) + ((size_t)b*Cn + m0)*Dn;
  __shared__ float As[2][128][32], Bs[2][128][32];
  __shared__ float qm[128], rm[128], ri[128];
  int tid = threadIdx.x;
  if (tid < 128){
    qm[tid] = (1.f - qmask[b*Qn + tid])*MASK_VAL;
    rm[tid] = g_rowmax[b*Cn + m0 + tid];
    ri[tid] = 1.f / g_rowsum[b*Cn + m0 + tid];
  }
  __syncthreads();
  int arow = tid >> 1, aj0 = (tid & 1)*2;
  int bkl = tid >> 4, bseg = tid & 15;
  float mm = rm[arow], rr = ri[arow];
  // preload chunk 0
  {
    int kg = aj0*4;
    float4 v = *(const float4*)&Sb[(size_t)(m0 + arow)*Qn + kg];
    float4 w = *(const float4*)&Sb[(size_t)(m0 + arow)*Qn + kg + 4];
    float4 a0 = make_float4(tf32_hi(__expf(v.x + qm[kg]   - mm)*rr),
                            tf32_hi(__expf(v.y + qm[kg+1] - mm)*rr),
                            tf32_hi(__expf(v.z + qm[kg+2] - mm)*rr),
                            tf32_hi(__expf(v.w + qm[kg+3] - mm)*rr));
    float4 a1 = make_float4(tf32_hi(__expf(w.x + qm[kg+4] - mm)*rr),
                            tf32_hi(__expf(w.y + qm[kg+5] - mm)*rr),
                            tf32_hi(__expf(w.z + qm[kg+6] - mm)*rr),
                            tf32_hi(__expf(w.w + qm[kg+7] - mm)*rr));
    storeA2(As[0], arow, aj0, a0, a1);
    const float* src = &Bm[(size_t)bkl*Dn + bseg*8];
    float4 w0 = *(const float4*)&src[0], w1 = *(const float4*)&src[4];
    float bv[8] = {tf32_hi(w0.x),tf32_hi(w0.y),tf32_hi(w0.z),tf32_hi(w0.w),
                   tf32_hi(w1.x),tf32_hi(w1.y),tf32_hi(w1.z),tf32_hi(w1.w)};
    storeB8(Bs[0], bseg, bkl, bv);
  }
  __syncthreads();
  int warp = tid >> 5, lane = tid & 31;
  int WM = warp >> 1, WN = warp & 1;
  int grp = lane >> 2, qd = lane & 3;
  int mb = WM*32, nb = WN*64;
  float acc[2][8][4] = {};
  for (int k0 = 0; k0 < 8; k0++){
    float4 av0, av1, bv0, bv1;
    bool nxt = (k0 < 7);
    if (nxt){
      int kn = (k0+1)*16;
      av0 = *(const float4*)&Sb[(size_t)(m0 + arow)*Qn + kn + aj0*4];
      av1 = *(const float4*)&Sb[(size_t)(m0 + arow)*Qn + kn + aj0*4 + 4];
      const float* sp = &Bm[(size_t)(kn + bkl)*Dn + bseg*8];
      bv0 = *(const float4*)&sp[0]; bv1 = *(const float4*)&sp[4];
    }
    mma_k16(As[k0&1], Bs[k0&1], acc, mb, nb, grp, qd);
    if (nxt){
      int nbuf = (k0+1)&1;
      int kg = (k0+1)*16 + aj0*4;
      float4 a0 = make_float4(tf32_hi(__expf(av0.x + qm[kg]   - mm)*rr),
                              tf32_hi(__expf(av0.y + qm[kg+1] - mm)*rr),
                              tf32_hi(__expf(av0.z + qm[kg+2] - mm)*rr),
                              tf32_hi(__expf(av0.w + qm[kg+3] - mm)*rr));
      float4 a1 = make_float4(tf32_hi(__expf(av1.x + qm[kg+4] - mm)*rr),
                              tf32_hi(__expf(av1.y + qm[kg+5] - mm)*rr),
                              tf32_hi(__expf(av1.z + qm[kg+6] - mm)*rr),
                              tf32_hi(__expf(av1.w + qm[kg+7] - mm)*rr));
      storeA2(As[nbuf], arow, aj0, a0, a1);
      float bv[8] = {tf32_hi(bv0.x),tf32_hi(bv0.y),tf32_hi(bv0.z),tf32_hi(bv0.w),
                     tf32_hi(bv1.x),tf32_hi(bv1.y),tf32_hi(bv1.z),tf32_hi(bv1.w)};
      storeB8(Bs[nbuf], bseg, bkl, bv);
    }
    __syncthreads();
  }
  #pragma unroll
  for (int mi = 0; mi < 2; mi++){
    int r = mb + mi*16 + grp;
    #pragma unroll
    for (int ni = 0; ni < 8; ni++){
      int col = nb + ni*8 + qd*2;
      *(float2*)&O[(size_t)r*Dn + col]     = make_float2(acc[mi][ni][0], acc[mi][ni][1]);
      *(float2*)&O[(size_t)(r+8)*Dn + col] = make_float2(acc[mi][ni][2], acc[mi][ni][3]);
    }
  }
}

// ---------------- feats = [v, c2q, v*c2q, v*q2c] @ cqa_W^T + b ----------------
// Source-grouped k-order: it -> (g = it>>2 k-column group, s = it&3 source).
// v and c2q chunks for each group are loaded ONCE and kept in registers;
// src2 (v*c2q) needs no global load, src3 reuses the v registers.
__global__ void __launch_bounds__(256,2) k_feats(const float* __restrict__ vfeats,
                                                 const float* __restrict__ cqa_b){
  size_t m0 = (size_t)blockIdx.x*128;
  __shared__ float As[2][128][32], Bs[2][128][32];
  __shared__ float cb[128];
  int tid = threadIdx.x;
  if (tid < 128) cb[tid] = cqa_b[tid];
  int arow = tid >> 1, aj0 = (tid & 1)*2;
  int bkl = tid >> 4, bseg = tid & 15;
  float4 vk0, vk1, ck0, ck1;  // persistent v / c2q chunk registers
  // preload it=0: g=0, s=0 -> vfeats chunk 0
  {
    size_t off0 = (m0 + arow)*(size_t)Dn + aj0*4;
    vk0 = *(const float4*)&vfeats[off0];
    vk1 = *(const float4*)&vfeats[off0+4];
    storeA2(As[0], arow, aj0, tf4(vk0), tf4(vk1));
    const float* srcp = &g_cqaWT[bkl*128 + bseg*8];  // B row s*128+g*16 = 0
    float4 w0 = *(const float4*)&srcp[0], w1 = *(const float4*)&srcp[4];
    float bv[8] = {tf32_hi(w0.x),tf32_hi(w0.y),tf32_hi(w0.z),tf32_hi(w0.w),
                   tf32_hi(w1.x),tf32_hi(w1.y),tf32_hi(w1.z),tf32_hi(w1.w)};
    storeB8(Bs[0], bseg, bkl, bv);
  }
  __syncthreads();
  int warp = tid >> 5, lane = tid & 31;
  int WM = warp >> 1, WN = warp & 1;
  int grp = lane >> 2, qd = lane & 3;
  int mb = WM*32, nb = WN*64;
  float acc[2][8][4] = {};
  #pragma unroll 4
  for (int it = 0; it < 32; it++){
    float4 av0, av1, bv0, bv1;
    int it2 = it + 1, g2 = it2 >> 2, s2 = it2 & 3;
    bool nxt = (it < 31);
    if (nxt){
      size_t off0 = (m0 + arow)*(size_t)Dn + g2*16 + aj0*4;
      if (s2 == 0)      { av0 = *(const float4*)&vfeats[off0]; av1 = *(const float4*)&vfeats[off0+4]; }
      else if (s2 == 1) { av0 = *(const float4*)&g_c2q[off0];  av1 = *(const float4*)&g_c2q[off0+4]; }
      else if (s2 == 3) { av0 = *(const float4*)&g_q2c[off0];  av1 = *(const float4*)&g_q2c[off0+4]; }
      // s2 == 2: no global load (v*c2q from registers)
      const float* sp = &g_cqaWT[(s2*128 + g2*16 + bkl)*128 + bseg*8];
      bv0 = *(const float4*)&sp[0]; bv1 = *(const float4*)&sp[4];
    }
    mma_k16(As[it&1], Bs[it&1], acc, mb, nb, grp, qd);
    if (nxt){
      int nbuf = it2 & 1;
      float4 a0, a1;
      if (s2 == 0)      { vk0 = av0; vk1 = av1; a0 = av0; a1 = av1; }
      else if (s2 == 1) { ck0 = av0; ck1 = av1; a0 = av0; a1 = av1; }
      else if (s2 == 2) { a0 = mul4(vk0, ck0); a1 = mul4(vk1, ck1); }
      else              { a0 = mul4(vk0, av0); a1 = mul4(vk1, av1); }
      storeA2(As[nbuf], arow, aj0, tf4(a0), tf4(a1));
      float bv[8] = {tf32_hi(bv0.x),tf32_hi(bv0.y),tf32_hi(bv0.z),tf32_hi(bv0.w),
                     tf32_hi(bv1.x),tf32_hi(bv1.y),tf32_hi(bv1.z),tf32_hi(bv1.w)};
      storeB8(Bs[nbuf], bseg, bkl, bv);
    }
    __syncthreads();
  }
  #pragma unroll
  for (int mi = 0; mi < 2; mi++){
    size_t r = m0 + mb + mi*16 + grp;
    #pragma unroll
    for (int ni = 0; ni < 8; ni++){
      int col = nb + ni*8 + qd*2;
      *(float2*)&g_feats[r*Dn + col]     = make_float2(acc[mi][ni][0] + cb[col], acc[mi][ni][1] + cb[col+1]);
      *(float2*)&g_feats[(r+8)*Dn + col] = make_float2(acc[mi][ni][2] + cb[col], acc[mi][ni][3] + cb[col+1]);
    }
  }
}

// ---------------- out = relu(feats @ ccW1^T + bias2[b]) (tf32, db, swizzled) ----------------
__global__ void __launch_bounds__(256,2) k_out(float* __restrict__ out){
  size_t m0 = (size_t)blockIdx.x*128;
  int bb = (int)(m0 >> 11);
  __shared__ float As[2][128][32], Bs[2][128][32];
  __shared__ float b2s[128];
  int tid = threadIdx.x;
  if (tid < 128) b2s[tid] = g_bias2[bb*Dn + tid];
  int arow = tid >> 1, aj0 = (tid & 1)*2;
  int bkl = tid >> 4, bseg = tid & 15;
  // preload chunk 0
  {
    float4 v0 = tf4(*(const float4*)&g_feats[(m0 + arow)*(size_t)Dn + aj0*4]);
    float4 v1 = tf4(*(const float4*)&g_feats[(m0 + arow)*(size_t)Dn + aj0*4 + 4]);
    storeA2(As[0], arow, aj0, v0, v1);
    const float* src = &g_ccWT[bkl*128 + bseg*8];
    float4 w0 = *(const float4*)&src[0], w1 = *(const float4*)&src[4];
    float bv[8] = {tf32_hi(w0.x),tf32_hi(w0.y),tf32_hi(w0.z),tf32_hi(w0.w),
                   tf32_hi(w1.x),tf32_hi(w1.y),tf32_hi(w1.z),tf32_hi(w1.w)};
    storeB8(Bs[0], bseg, bkl, bv);
  }
  __syncthreads();
  int warp = tid >> 5, lane = tid & 31;
  int WM = warp >> 1, WN = warp & 1;
  int grp = lane >> 2, qd = lane & 3;
  int mb = WM*32, nb = WN*64;
  float acc[2][8][4] = {};
  for (int k0 = 0; k0 < 8; k0++){
    float4 av0, av1, bv0, bv1;
    bool nxt = (k0 < 7);
    if (nxt){
      int kn = (k0+1)*16;
      av0 = *(const float4*)&g_feats[(m0 + arow)*(size_t)Dn + kn + aj0*4];
      av1 = *(const float4*)&g_feats[(m0 + arow)*(size_t)Dn + kn + aj0*4 + 4];
      const float* sp = &g_ccWT[(kn + bkl)*128 + bseg*8];
      bv0 = *(const float4*)&sp[0]; bv1 = *(const float4*)&sp[4];
    }
    mma_k16(As[k0&1], Bs[k0&1], acc, mb, nb, grp, qd);
    if (nxt){
      int nbuf = (k0+1)&1;
      storeA2(As[nbuf], arow, aj0, tf4(av0), tf4(av1));
      float bv[8] = {tf32_hi(bv0.x),tf32_hi(bv0.y),tf32_hi(bv0.z),tf32_hi(bv0.w),
                     tf32_hi(bv1.x),tf32_hi(bv1.y),tf32_hi(bv1.z),tf32_hi(bv1.w)};
      storeB8(Bs[nbuf], bseg, bkl, bv);
    }
    __syncthreads();
  }
  #pragma unroll
  for (int mi = 0; mi < 2; mi++){
    size_t r = m0 + mb + mi*16 + grp;
    #pragma unroll
    for (int ni = 0; ni < 8; ni++){
      int col = nb + ni*8 + qd*2;
      float2 w0 = make_float2(fmaxf(acc[mi][ni][0] + b2s[col], 0.f), fmaxf(acc[mi][ni][1] + b2s[col+1], 0.f));
      float2 w1 = make_float2(fmaxf(acc[mi][ni][2] + b2s[col], 0.f), fmaxf(acc[mi][ni][3] + b2s[col+1], 0.f));
      *(float2*)&out[r*Dn + col]     = w0;
      *(float2*)&out[(r+8)*Dn + col] = w1;
    }
  }
}

// ---------------- launch ----------------
extern "C" void kernel_launch(void* const* d_in, const int* in_sizes, int n_in,
                              void* d_out, int out_size){
  const float* vfeats = (const float*)d_in[0];
  const float* qfeats = (const float*)d_in[1];
  const float* vmask  = (const float*)d_in[2];
  const float* qmask  = (const float*)d_in[3];
  const float* w4C    = (const float*)d_in[4];
  const float* w4Q    = (const float*)d_in[5];
  const float* w4mlu  = (const float*)d_in[6];
  const float* cqa_W  = (const float*)d_in[7];
  const float* cqa_b  = (const float*)d_in[8];
  const float* wp     = (const float*)d_in[9];
  const float* cc_W   = (const float*)d_in[10];
  const float* cc_b   = (const float*)d_in[11];
  float* out = (float*)d_out;

  k_prepW<<<128, 256>>>(cqa_W, cc_W);
  k_beff<<<Bn, 128>>>(qfeats, w4mlu, w4C);
  k_pool<<<Bn, 128>>>(qfeats, w4Q, wp, qmask, cc_W, cc_b);
  k_score<<<dim3(Cn/128, Bn), 256>>>(vfeats, vmask, qmask);
  k_colcombine<<<Bn, 128>>>();
  k_tmp<<<dim3(4, Bn), 256>>>(vfeats, vmask);
  k_tmp_reduce<<<(Bn*Qn*Dn)/256, 256>>>();
  k_pgemm<0><<<dim3(Cn/128, Bn), 256>>>(qfeats, qmask);
  k_pgemm<1><<<dim3(Cn/128, Bn), 256>>>(qfeats, qmask);
  k_feats<<<(Bn*Cn)/128, 256>>>(vfeats, cqa_b);
  k_out<<<(Bn*Cn)/128, 256>>>(out);
}

// round 15
// speedup vs baseline: 1.5219x; 1.0037x over previous
#include <cuda_runtime.h>
#include <math.h>

#define Bn 64
#define Cn 2048
#define Qn 128
#define Dn 128
#define MASK_VAL (-1e30f)

// ---------------- scratch ----------------
__device__ float g_score[(size_t)Bn*Cn*Qn];
__device__ float g_Beff [(size_t)Bn*Dn*Qn];     // tf32-pre-rounded
__device__ float g_bq   [Bn*Qn];
__device__ float g_rowmax[Bn*Cn];
__device__ float g_rowsum[Bn*Cn];
__device__ float g_colpm[Bn*16*Qn];
__device__ float g_colps[Bn*16*Qn];
__device__ float g_colmax[Bn*Qn];
__device__ float g_colsum[Bn*Qn];
__device__ float g_tmp_part[(size_t)Bn*4*Qn*Dn];
__device__ float g_tmp [(size_t)Bn*Qn*Dn];      // tf32-pre-rounded
__device__ float g_bias2[Bn*Dn];
__device__ float g_c2q [(size_t)Bn*Cn*Dn];
__device__ float g_q2c [(size_t)Bn*Cn*Dn];
__device__ float g_feats[(size_t)Bn*Cn*Dn];     // tf32-pre-rounded
__device__ float g_qfT [(size_t)Bn*Qn*Dn];      // tf32-pre-rounded qfeats
__device__ float g_cqaWT[512*128];              // tf32-pre-rounded
__device__ float g_ccWT [128*128];              // tf32-pre-rounded

// ---------------- tf32 helpers ----------------
__device__ __forceinline__ unsigned cvt_tf32(float x){
  unsigned u; asm("cvt.rna.tf32.f32 %0, %1;" : "=r"(u) : "f"(x)); return u;
}
__device__ __forceinline__ float tf32_hi(float x){ return __uint_as_float(cvt_tf32(x)); }

#define MMA_TF32(D, A0,A1,A2,A3, B0,B1) \
  asm volatile("mma.sync.aligned.m16n8k8.row.col.f32.tf32.tf32.f32 " \
      "{%0,%1,%2,%3}, {%4,%5,%6,%7}, {%8,%9}, {%0,%1,%2,%3};" \
      : "+f"(D[0]), "+f"(D[1]), "+f"(D[2]), "+f"(D[3]) \
      : "r"(A0), "r"(A1), "r"(A2), "r"(A3), "r"(B0), "r"(B1))

// ---- swizzled fragment tile [rows][32]:
// element k (0..15) of row n stored at quad ((k&3) + (n&7) + (n>>3)) & 7, offset k>>2.

__device__ __forceinline__ void storeB8(float (*T)[32], int bseg, int bkl, const float* v8){
  int bq = bkl >> 2, bc = bkl & 3;
  int e0 = bseg*8;
  #pragma unroll
  for (int e = 0; e < 8; e++)
    T[e0+e][((bc + e + bseg) & 7)*4 + bq] = v8[e];
}
__device__ __forceinline__ void storeA2(float (*T)[32], int arow, int aj0,
                                        const float4& v0, const float4& v1){
  int ga = (arow & 7) + (arow >> 3);
  const float* p0 = (const float*)&v0;
  const float* p1 = (const float*)&v1;
  #pragma unroll
  for (int t = 0; t < 4; t++){
    T[arow][((t + ga) & 7)*4 + aj0]     = p0[t];
    T[arow][((t + ga) & 7)*4 + aj0 + 1] = p1[t];
  }
}

// Per-warp 32x64 tile MMA over a k16 chunk, swizzled tiles.
__device__ __forceinline__ void mma_k16(const float (*As)[32], const float (*Bs)[32],
                                        float acc[2][8][4], int mb, int nb, int grp, int qd){
  int baseq = qd + grp;
  int mh = mb >> 3, nh = nb >> 3;
  float4 va[2][2];
  #pragma unroll
  for (int mi = 0; mi < 2; mi++){
    int r = mb + mi*16 + grp;
    va[mi][0] = *(const float4*)&As[r][((baseq + mh + mi*2) & 7)*4];
    va[mi][1] = *(const float4*)&As[r+8][((baseq + mh + mi*2 + 1) & 7)*4];
  }
  float4 vb[8];
  #pragma unroll
  for (int ni = 0; ni < 8; ni++){
    int n = nb + ni*8 + grp;
    vb[ni] = *(const float4*)&Bs[n][((baseq + nh + ni) & 7)*4];
  }
  #pragma unroll
  for (int mi = 0; mi < 2; mi++)
    #pragma unroll
    for (int ni = 0; ni < 8; ni++){
      MMA_TF32(acc[mi][ni],
        __float_as_uint(va[mi][0].x), __float_as_uint(va[mi][1].x),
        __float_as_uint(va[mi][0].y), __float_as_uint(va[mi][1].y),
        __float_as_uint(vb[ni].x),    __float_as_uint(vb[ni].y));
      MMA_TF32(acc[mi][ni],
        __float_as_uint(va[mi][0].z), __float_as_uint(va[mi][1].z),
        __float_as_uint(va[mi][0].w), __float_as_uint(va[mi][1].w),
        __float_as_uint(vb[ni].z),    __float_as_uint(vb[ni].w));
    }
}

__device__ __forceinline__ float4 tf4(float4 v){
  return make_float4(tf32_hi(v.x), tf32_hi(v.y), tf32_hi(v.z), tf32_hi(v.w));
}
__device__ __forceinline__ float4 mul4(float4 a, float4 b){
  return make_float4(a.x*b.x, a.y*b.y, a.z*b.z, a.w*b.w);
}

// ---------------- prep kernels ----------------
// Weights + qf copy are pre-rounded to tf32 here (idempotent with the cvt the
// GEMM loops used to do at load time -> downstream MMAs see identical bits).
__global__ void k_prepW(const float* __restrict__ cqaW, const float* __restrict__ ccW,
                        const float* __restrict__ qf){
  int tid = blockIdx.x*blockDim.x + threadIdx.x;
  int stride = gridDim.x*blockDim.x;
  for (int idx = tid; idx < 512*128; idx += stride){
    int k = idx >> 7, n = idx & 127;
    g_cqaWT[idx] = tf32_hi(cqaW[n*512 + k]);
  }
  for (int idx = tid; idx < 128*128; idx += stride){
    int k = idx >> 7, n = idx & 127;
    g_ccWT[idx] = tf32_hi(ccW[n*256 + k]);
  }
  for (int idx = tid; idx < Bn*Qn*Dn; idx += stride)
    g_qfT[idx] = tf32_hi(qf[idx]);
}

__global__ void __launch_bounds__(128) k_beff(const float* __restrict__ qf,
                                              const float* __restrict__ w4mlu,
                                              const float* __restrict__ w4C){
  int b = blockIdx.x, tid = threadIdx.x;
  __shared__ float s[64][129];
  for (int q0 = 0; q0 < Qn; q0 += 64){
    for (int r = 0; r < 64; r++)
      s[r][tid] = qf[((size_t)b*Qn + q0 + r)*Dn + tid];
    __syncthreads();
    for (int it = 0; it < 64; it++){
      int idx = it*128 + tid;
      int d = idx >> 6, q = idx & 63;
      g_Beff[(size_t)b*Dn*Qn + (size_t)d*Qn + q0 + q] = tf32_hi(s[q][d]*w4mlu[d] + w4C[d]);
    }
    __syncthreads();
  }
}

__global__ void __launch_bounds__(128) k_pool(const float* __restrict__ qf,
                                              const float* __restrict__ w4Q,
                                              const float* __restrict__ wp,
                                              const float* __restrict__ qmask,
                                              const float* __restrict__ ccW,
                                              const float* __restrict__ ccb){
  int b = blockIdx.x, tid = threadIdx.x;
  __shared__ float red[128];
  __shared__ float alpha[128];
  __shared__ float pooled[128];
  const float* qrow = qf + ((size_t)b*Qn + tid)*Dn;
  float bq = 0.f, lg = 0.f;
  for (int d = 0; d < Dn; d++){ float v = qrow[d]; bq += v*w4Q[d]; lg += v*wp[d]; }
  g_bq[b*Qn + tid] = bq;
  float x = lg + (1.f - qmask[b*Qn + tid])*MASK_VAL;
  red[tid] = x; __syncthreads();
  for (int s = 64; s > 0; s >>= 1){ if (tid < s) red[tid] = fmaxf(red[tid], red[tid+s]); __syncthreads(); }
  float m = red[0]; __syncthreads();
  float e = __expf(x - m);
  red[tid] = e; __syncthreads();
  for (int s = 64; s > 0; s >>= 1){ if (tid < s) red[tid] += red[tid+s]; __syncthreads(); }
  float ssum = red[0];
  alpha[tid] = e / ssum;
  __syncthreads();
  float p = 0.f;
  for (int q = 0; q < Qn; q++) p += qf[((size_t)b*Qn + q)*Dn + tid]*alpha[q];
  pooled[tid] = p; __syncthreads();
  float acc = ccb[tid];
  for (int k = 0; k < Dn; k++) acc += pooled[k]*ccW[tid*256 + 128 + k];
  g_bias2[b*Dn + tid] = acc;
}

// ---------------- score GEMM (tf32, db, swizzled) + fused softmax stats ----------------
__global__ void __launch_bounds__(256,2) k_score(const float* __restrict__ vfeats,
                                                 const float* __restrict__ vmask,
                                                 const float* __restrict__ qmask){
  int b  = blockIdx.y, bx = blockIdx.x;
  int m0 = bx*128;
  const float* A  = vfeats + (size_t)b*Cn*Dn;
  const float* Bm = g_Beff + (size_t)b*Dn*Qn;   // pre-rounded
  float* Sout = g_score + (size_t)b*Cn*Qn;
  __shared__ float As[2][128][32], Bs[2][128][32];
  __shared__ float bqs[128], qm[128], vm[128];
  __shared__ float smRm[128][2], smRs[128][2];
  __shared__ float smCm[128][4], smCs[128][4];
  int tid = threadIdx.x;
  if (tid < 128){
    bqs[tid] = g_bq[b*Qn + tid];
    qm[tid]  = (1.f - qmask[b*Qn + tid])*MASK_VAL;
    vm[tid]  = (1.f - vmask[b*Cn + m0 + tid])*MASK_VAL;
  }
  int arow = tid >> 1, aj0 = (tid & 1)*2;
  int bkl = tid >> 4, bseg = tid & 15;
  // preload chunk 0
  {
    float4 v0 = tf4(*(const float4*)&A[(size_t)(m0 + arow)*Dn + aj0*4]);
    float4 v1 = tf4(*(const float4*)&A[(size_t)(m0 + arow)*Dn + aj0*4 + 4]);
    storeA2(As[0], arow, aj0, v0, v1);
    const float* src = &Bm[(size_t)bkl*Qn + bseg*8];
    float4 w0 = *(const float4*)&src[0], w1 = *(const float4*)&src[4];
    float vv[8] = {w0.x,w0.y,w0.z,w0.w,w1.x,w1.y,w1.z,w1.w};
    storeB8(Bs[0], bseg, bkl, vv);
  }
  __syncthreads();
  int warp = tid >> 5, lane = tid & 31;
  int WM = warp >> 1, WN = warp & 1;
  int grp = lane >> 2, qd = lane & 3;
  int mb = WM*32, nb = WN*64;
  float acc[2][8][4] = {};
  for (int k0 = 0; k0 < 8; k0++){
    float4 av0, av1, bv0, bv1;
    bool nxt = (k0 < 7);
    if (nxt){
      int kn = (k0+1)*16;
      av0 = *(const float4*)&A[(size_t)(m0 + arow)*Dn + kn + aj0*4];
      av1 = *(const float4*)&A[(size_t)(m0 + arow)*Dn + kn + aj0*4 + 4];
      const float* sp = &Bm[(size_t)(kn + bkl)*Qn + bseg*8];
      bv0 = *(const float4*)&sp[0]; bv1 = *(const float4*)&sp[4];
    }
    mma_k16(As[k0&1], Bs[k0&1], acc, mb, nb, grp, qd);
    if (nxt){
      int nbuf = (k0+1)&1;
      storeA2(As[nbuf], arow, aj0, tf4(av0), tf4(av1));
      float vv[8] = {bv0.x,bv0.y,bv0.z,bv0.w,bv1.x,bv1.y,bv1.z,bv1.w};
      storeB8(Bs[nbuf], bseg, bkl, vv);
    }
    __syncthreads();
  }
  // ---- epilogue: add bq, write score, fused row/col softmax stats ----
  #pragma unroll
  for (int mi = 0; mi < 2; mi++){
    int r = m0 + mb + mi*16 + grp;
    #pragma unroll
    for (int ni = 0; ni < 8; ni++){
      int c0 = nb + ni*8 + qd*2;
      acc[mi][ni][0] += bqs[c0]; acc[mi][ni][1] += bqs[c0+1];
      acc[mi][ni][2] += bqs[c0]; acc[mi][ni][3] += bqs[c0+1];
      *(float2*)&Sout[(size_t)r*Qn + c0]     = make_float2(acc[mi][ni][0], acc[mi][ni][1]);
      *(float2*)&Sout[(size_t)(r+8)*Qn + c0] = make_float2(acc[mi][ni][2], acc[mi][ni][3]);
    }
  }
  // row stats
  #pragma unroll
  for (int s = 0; s < 4; s++){
    int mi = s >> 1, e0 = (s & 1)*2;
    float m = -INFINITY;
    #pragma unroll
    for (int ni = 0; ni < 8; ni++){
      int c0 = nb + ni*8 + qd*2;
      m = fmaxf(m, acc[mi][ni][e0]   + qm[c0]);
      m = fmaxf(m, acc[mi][ni][e0+1] + qm[c0+1]);
    }
    m = fmaxf(m, __shfl_xor_sync(0xffffffffu, m, 1));
    m = fmaxf(m, __shfl_xor_sync(0xffffffffu, m, 2));
    float ssum = 0.f;
    #pragma unroll
    for (int ni = 0; ni < 8; ni++){
      int c0 = nb + ni*8 + qd*2;
      ssum += __expf(acc[mi][ni][e0]   + qm[c0]   - m);
      ssum += __expf(acc[mi][ni][e0+1] + qm[c0+1] - m);
    }
    ssum += __shfl_xor_sync(0xffffffffu, ssum, 1);
    ssum += __shfl_xor_sync(0xffffffffu, ssum, 2);
    if (qd == 0){
      int rr = mb + mi*16 + (s & 1)*8 + grp;
      smRm[rr][WN] = m; smRs[rr][WN] = ssum;
    }
  }
  // col stats (partial over this block's 128 rows)
  float vmr[4] = { vm[mb+grp], vm[mb+grp+8], vm[mb+16+grp], vm[mb+16+grp+8] };
  #pragma unroll
  for (int g = 0; g < 4; g++){
    float cm4[4], cs4[4];
    #pragma unroll
    for (int u = 0; u < 4; u++){
      int idx = g*4 + u;
      int ni = idx >> 1, e = idx & 1;
      float m = fmaxf(fmaxf(acc[0][ni][e] + vmr[0], acc[0][ni][e+2] + vmr[1]),
                      fmaxf(acc[1][ni][e] + vmr[2], acc[1][ni][e+2] + vmr[3]));
      cm4[u] = m;
    }
    #pragma unroll
    for (int o = 4; o <= 16; o <<= 1)
      #pragma unroll
      for (int u = 0; u < 4; u++)
        cm4[u] = fmaxf(cm4[u], __shfl_xor_sync(0xffffffffu, cm4[u], o));
    #pragma unroll
    for (int u = 0; u < 4; u++){
      int idx = g*4 + u;
      int ni = idx >> 1, e = idx & 1;
      cs4[u] = __expf(acc[0][ni][e]   + vmr[0] - cm4[u])
             + __expf(acc[0][ni][e+2] + vmr[1] - cm4[u])
             + __expf(acc[1][ni][e]   + vmr[2] - cm4[u])
             + __expf(acc[1][ni][e+2] + vmr[3] - cm4[u]);
    }
    #pragma unroll
    for (int o = 4; o <= 16; o <<= 1)
      #pragma unroll
      for (int u = 0; u < 4; u++)
        cs4[u] += __shfl_xor_sync(0xffffffffu, cs4[u], o);
    if (grp == 0){
      #pragma unroll
      for (int u = 0; u < 4; u++){
        int idx = g*4 + u;
        int ni = idx >> 1, e = idx & 1;
        int col = nb + ni*8 + qd*2 + e;
        smCm[col][WM] = cm4[u]; smCs[col][WM] = cs4[u];
      }
    }
  }
  __syncthreads();
  if (tid < 128){
    float ma = smRm[tid][0], mbv = smRm[tid][1];
    float M = fmaxf(ma, mbv);
    float S = smRs[tid][0]*__expf(ma - M) + smRs[tid][1]*__expf(mbv - M);
    g_rowmax[b*Cn + m0 + tid] = M;
    g_rowsum[b*Cn + m0 + tid] = S;
    float cm2 = -INFINITY, cs2 = 0.f;
    #pragma unroll
    for (int w = 0; w < 4; w++){
      float pm = smCm[tid][w], ps = smCs[tid][w];
      float nm = fmaxf(cm2, pm);
      cs2 = cs2*__expf(cm2 - nm) + ps*__expf(pm - nm);
      cm2 = nm;
    }
    g_colpm[(b*16 + bx)*Qn + tid] = cm2;
    g_colps[(b*16 + bx)*Qn + tid] = cs2;
  }
}

__global__ void __launch_bounds__(128) k_colcombine(){
  int b = blockIdx.x, q = threadIdx.x;
  float m = -INFINITY, s = 0.f;
  for (int ch = 0; ch < 16; ch++){
    float pm = g_colpm[(b*16 + ch)*Qn + q];
    float ps = g_colps[(b*16 + ch)*Qn + q];
    float nm = fmaxf(m, pm);
    s = s*__expf(m - nm) + ps*__expf(pm - nm);
    m = nm;
  }
  g_colmax[b*Qn + q] = m;
  g_colsum[b*Qn + q] = s;
}

// ---------------- tmp = score_t^T @ V (tf32, split-K x4, db, swizzled) ----------------
__global__ void __launch_bounds__(256,2) k_tmp(const float* __restrict__ vfeats,
                                               const float* __restrict__ vmask){
  int b = blockIdx.y, ch = blockIdx.x;
  const float* Sb = g_score + (size_t)b*Cn*Qn;
  const float* V  = vfeats  + (size_t)b*Cn*Dn;
  __shared__ float As[2][128][32], Bs[2][128][32];
  __shared__ float cm[128];
  int tid = threadIdx.x;
  if (tid < 128) cm[tid] = g_colmax[b*Qn + tid];
  __syncthreads();
  int bkl = tid >> 4, bseg = tid & 15;
  int e0 = bseg*8;
  int cbase = ch*512;
  // preload chunk 0
  {
    int c = cbase + bkl;
    float mv = (1.f - vmask[b*Cn + c])*MASK_VAL;
    float4 s0 = *(const float4*)&Sb[(size_t)c*Qn + e0];
    float4 s1 = *(const float4*)&Sb[(size_t)c*Qn + e0 + 4];
    float av[8] = {tf32_hi(__expf(s0.x+mv-cm[e0+0])), tf32_hi(__expf(s0.y+mv-cm[e0+1])),
                   tf32_hi(__expf(s0.z+mv-cm[e0+2])), tf32_hi(__expf(s0.w+mv-cm[e0+3])),
                   tf32_hi(__expf(s1.x+mv-cm[e0+4])), tf32_hi(__expf(s1.y+mv-cm[e0+5])),
                   tf32_hi(__expf(s1.z+mv-cm[e0+6])), tf32_hi(__expf(s1.w+mv-cm[e0+7]))};
    storeB8(As[0], bseg, bkl, av);
    float4 v0 = *(const float4*)&V[(size_t)c*Dn + e0];
    float4 v1 = *(const float4*)&V[(size_t)c*Dn + e0 + 4];
    float bv[8] = {tf32_hi(v0.x),tf32_hi(v0.y),tf32_hi(v0.z),tf32_hi(v0.w),
                   tf32_hi(v1.x),tf32_hi(v1.y),tf32_hi(v1.z),tf32_hi(v1.w)};
    storeB8(Bs[0], bseg, bkl, bv);
  }
  __syncthreads();
  int warp = tid >> 5, lane = tid & 31;
  int WM = warp >> 1, WN = warp & 1;
  int grp = lane >> 2, qd = lane & 3;
  int mb = WM*32, nb = WN*64;
  float acc[2][8][4] = {};
  for (int kt = 0; kt < 32; kt++){
    float4 s0n, s1n, v0n, v1n; float mvn = 0.f;
    bool nxt = (kt < 31);
    if (nxt){
      int c = cbase + (kt+1)*16 + bkl;
      mvn = (1.f - vmask[b*Cn + c])*MASK_VAL;
      s0n = *(const float4*)&Sb[(size_t)c*Qn + e0];
      s1n = *(const float4*)&Sb[(size_t)c*Qn + e0 + 4];
      v0n = *(const float4*)&V[(size_t)c*Dn + e0];
      v1n = *(const float4*)&V[(size_t)c*Dn + e0 + 4];
    }
    mma_k16(As[kt&1], Bs[kt&1], acc, mb, nb, grp, qd);
    if (nxt){
      int nbuf = (kt+1)&1;
      float av[8] = {tf32_hi(__expf(s0n.x+mvn-cm[e0+0])), tf32_hi(__expf(s0n.y+mvn-cm[e0+1])),
                     tf32_hi(__expf(s0n.z+mvn-cm[e0+2])), tf32_hi(__expf(s0n.w+mvn-cm[e0+3])),
                     tf32_hi(__expf(s1n.x+mvn-cm[e0+4])), tf32_hi(__expf(s1n.y+mvn-cm[e0+5])),
                     tf32_hi(__expf(s1n.z+mvn-cm[e0+6])), tf32_hi(__expf(s1n.w+mvn-cm[e0+7]))};
      storeB8(As[nbuf], bseg, bkl, av);
      float bv[8] = {tf32_hi(v0n.x),tf32_hi(v0n.y),tf32_hi(v0n.z),tf32_hi(v0n.w),
                     tf32_hi(v1n.x),tf32_hi(v1n.y),tf32_hi(v1n.z),tf32_hi(v1n.w)};
      storeB8(Bs[nbuf], bseg, bkl, bv);
    }
    __syncthreads();
  }
  float* P = g_tmp_part + (size_t)(b*4 + ch)*Qn*Dn;
  #pragma unroll
  for (int mi = 0; mi < 2; mi++){
    int r = mb + mi*16 + grp;
    #pragma unroll
    for (int ni = 0; ni < 8; ni++){
      int col = nb + ni*8 + qd*2;
      *(float2*)&P[(size_t)r*Dn + col]     = make_float2(acc[mi][ni][0], acc[mi][ni][1]);
      *(float2*)&P[(size_t)(r+8)*Dn + col] = make_float2(acc[mi][ni][2], acc[mi][ni][3]);
    }
  }
}

__global__ void __launch_bounds__(256) k_tmp_reduce(){
  int idx = blockIdx.x*256 + threadIdx.x;
  int b = idx >> 14;
  int r = idx & 16383;
  int q = r >> 7;
  size_t base = (size_t)b*4*Qn*Dn + r;
  float s = g_tmp_part[base] + g_tmp_part[base + Qn*Dn]
          + g_tmp_part[base + 2*Qn*Dn] + g_tmp_part[base + 3*Qn*Dn];
  g_tmp[idx] = tf32_hi(s / g_colsum[b*Qn + q]);   // pre-round for pgemm<1> B
}

// ---------------- P @ B (tf32, db, swizzled): W=0: c2q = P@qfT, W=1: q2c = P@tmp ----------------
// B operands are pre-rounded tf32 -> no cvt in the loop.
template<int W>
__global__ void __launch_bounds__(256,2) k_pgemm(const float* __restrict__ qmask){
  int b = blockIdx.y; int m0 = blockIdx.x*128;
  const float* Sb = g_score + (size_t)b*Cn*Qn;
  const float* Bm = (W == 0 ? (const float*)g_qfT : (const float*)g_tmp) + (size_t)b*Qn*Dn;
  float* O = (W == 0 ? g_c2q : g_q2c) + ((size_t)b*Cn + m0)*Dn;
  __shared__ float As[2][128][32], Bs[2][128][32];
  __shared__ float qm[128], rm[128], ri[128];
  int tid = threadIdx.x;
  if (tid < 128){
    qm[tid] = (1.f - qmask[b*Qn + tid])*MASK_VAL;
    rm[tid] = g_rowmax[b*Cn + m0 + tid];
    ri[tid] = 1.f / g_rowsum[b*Cn + m0 + tid];
  }
  __syncthreads();
  int arow = tid >> 1, aj0 = (tid & 1)*2;
  int bkl = tid >> 4, bseg = tid & 15;
  float mm = rm[arow], rr = ri[arow];
  // preload chunk 0
  {
    int kg = aj0*4;
    float4 v = *(const float4*)&Sb[(size_t)(m0 + arow)*Qn + kg];
    float4 w = *(const float4*)&Sb[(size_t)(m0 + arow)*Qn + kg + 4];
    float4 a0 = make_float4(tf32_hi(__expf(v.x + qm[kg]   - mm)*rr),
                            tf32_hi(__expf(v.y + qm[kg+1] - mm)*rr),
                            tf32_hi(__expf(v.z + qm[kg+2] - mm)*rr),
                            tf32_hi(__expf(v.w + qm[kg+3] - mm)*rr));
    float4 a1 = make_float4(tf32_hi(__expf(w.x + qm[kg+4] - mm)*rr),
                            tf32_hi(__expf(w.y + qm[kg+5] - mm)*rr),
                            tf32_hi(__expf(w.z + qm[kg+6] - mm)*rr),
                            tf32_hi(__expf(w.w + qm[kg+7] - mm)*rr));
    storeA2(As[0], arow, aj0, a0, a1);
    const float* src = &Bm[(size_t)bkl*Dn + bseg*8];
    float4 w0 = *(const float4*)&src[0], w1 = *(const float4*)&src[4];
    float bv[8] = {w0.x,w0.y,w0.z,w0.w,w1.x,w1.y,w1.z,w1.w};
    storeB8(Bs[0], bseg, bkl, bv);
  }
  __syncthreads();
  int warp = tid >> 5, lane = tid & 31;
  int WM = warp >> 1, WN = warp & 1;
  int grp = lane >> 2, qd = lane & 3;
  int mb = WM*32, nb = WN*64;
  float acc[2][8][4] = {};
  for (int k0 = 0; k0 < 8; k0++){
    float4 av0, av1, bv0, bv1;
    bool nxt = (k0 < 7);
    if (nxt){
      int kn = (k0+1)*16;
      av0 = *(const float4*)&Sb[(size_t)(m0 + arow)*Qn + kn + aj0*4];
      av1 = *(const float4*)&Sb[(size_t)(m0 + arow)*Qn + kn + aj0*4 + 4];
      const float* sp = &Bm[(size_t)(kn + bkl)*Dn + bseg*8];
      bv0 = *(const float4*)&sp[0]; bv1 = *(const float4*)&sp[4];
    }
    mma_k16(As[k0&1], Bs[k0&1], acc, mb, nb, grp, qd);
    if (nxt){
      int nbuf = (k0+1)&1;
      int kg = (k0+1)*16 + aj0*4;
      float4 a0 = make_float4(tf32_hi(__expf(av0.x + qm[kg]   - mm)*rr),
                              tf32_hi(__expf(av0.y + qm[kg+1] - mm)*rr),
                              tf32_hi(__expf(av0.z + qm[kg+2] - mm)*rr),
                              tf32_hi(__expf(av0.w + qm[kg+3] - mm)*rr));
      float4 a1 = make_float4(tf32_hi(__expf(av1.x + qm[kg+4] - mm)*rr),
                              tf32_hi(__expf(av1.y + qm[kg+5] - mm)*rr),
                              tf32_hi(__expf(av1.z + qm[kg+6] - mm)*rr),
                              tf32_hi(__expf(av1.w + qm[kg+7] - mm)*rr));
      storeA2(As[nbuf], arow, aj0, a0, a1);
      float bv[8] = {bv0.x,bv0.y,bv0.z,bv0.w,bv1.x,bv1.y,bv1.z,bv1.w};
      storeB8(Bs[nbuf], bseg, bkl, bv);
    }
    __syncthreads();
  }
  #pragma unroll
  for (int mi = 0; mi < 2; mi++){
    int r = mb + mi*16 + grp;
    #pragma unroll
    for (int ni = 0; ni < 8; ni++){
      int col = nb + ni*8 + qd*2;
      *(float2*)&O[(size_t)r*Dn + col]     = make_float2(acc[mi][ni][0], acc[mi][ni][1]);
      *(float2*)&O[(size_t)(r+8)*Dn + col] = make_float2(acc[mi][ni][2], acc[mi][ni][3]);
    }
  }
}

// ---------------- feats = [v, c2q, v*c2q, v*q2c] @ cqa_W^T + b ----------------
// Source-grouped k-order; B (cqaWT) is pre-rounded -> no cvt in loop.
// Epilogue pre-rounds g_feats for k_out's A side.
__global__ void __launch_bounds__(256,2) k_feats(const float* __restrict__ vfeats,
                                                 const float* __restrict__ cqa_b){
  size_t m0 = (size_t)blockIdx.x*128;
  __shared__ float As[2][128][32], Bs[2][128][32];
  __shared__ float cb[128];
  int tid = threadIdx.x;
  if (tid < 128) cb[tid] = cqa_b[tid];
  int arow = tid >> 1, aj0 = (tid & 1)*2;
  int bkl = tid >> 4, bseg = tid & 15;
  float4 vk0, vk1, ck0, ck1;
  // preload it=0: g=0, s=0 -> vfeats chunk 0
  {
    size_t off0 = (m0 + arow)*(size_t)Dn + aj0*4;
    vk0 = *(const float4*)&vfeats[off0];
    vk1 = *(const float4*)&vfeats[off0+4];
    storeA2(As[0], arow, aj0, tf4(vk0), tf4(vk1));
    const float* srcp = &g_cqaWT[bkl*128 + bseg*8];
    float4 w0 = *(const float4*)&srcp[0], w1 = *(const float4*)&srcp[4];
    float bv[8] = {w0.x,w0.y,w0.z,w0.w,w1.x,w1.y,w1.z,w1.w};
    storeB8(Bs[0], bseg, bkl, bv);
  }
  __syncthreads();
  int warp = tid >> 5, lane = tid & 31;
  int WM = warp >> 1, WN = warp & 1;
  int grp = lane >> 2, qd = lane & 3;
  int mb = WM*32, nb = WN*64;
  float acc[2][8][4] = {};
  #pragma unroll 4
  for (int it = 0; it < 32; it++){
    float4 av0, av1, bv0, bv1;
    int it2 = it + 1, g2 = it2 >> 2, s2 = it2 & 3;
    bool nxt = (it < 31);
    if (nxt){
      size_t off0 = (m0 + arow)*(size_t)Dn + g2*16 + aj0*4;
      if (s2 == 0)      { av0 = *(const float4*)&vfeats[off0]; av1 = *(const float4*)&vfeats[off0+4]; }
      else if (s2 == 1) { av0 = *(const float4*)&g_c2q[off0];  av1 = *(const float4*)&g_c2q[off0+4]; }
      else if (s2 == 3) { av0 = *(const float4*)&g_q2c[off0];  av1 = *(const float4*)&g_q2c[off0+4]; }
      const float* sp = &g_cqaWT[(s2*128 + g2*16 + bkl)*128 + bseg*8];
      bv0 = *(const float4*)&sp[0]; bv1 = *(const float4*)&sp[4];
    }
    mma_k16(As[it&1], Bs[it&1], acc, mb, nb, grp, qd);
    if (nxt){
      int nbuf = it2 & 1;
      float4 a0, a1;
      if (s2 == 0)      { vk0 = av0; vk1 = av1; a0 = av0; a1 = av1; }
      else if (s2 == 1) { ck0 = av0; ck1 = av1; a0 = av0; a1 = av1; }
      else if (s2 == 2) { a0 = mul4(vk0, ck0); a1 = mul4(vk1, ck1); }
      else              { a0 = mul4(vk0, av0); a1 = mul4(vk1, av1); }
      storeA2(As[nbuf], arow, aj0, tf4(a0), tf4(a1));
      float bv[8] = {bv0.x,bv0.y,bv0.z,bv0.w,bv1.x,bv1.y,bv1.z,bv1.w};
      storeB8(Bs[nbuf], bseg, bkl, bv);
    }
    __syncthreads();
  }
  #pragma unroll
  for (int mi = 0; mi < 2; mi++){
    size_t r = m0 + mb + mi*16 + grp;
    #pragma unroll
    for (int ni = 0; ni < 8; ni++){
      int col = nb + ni*8 + qd*2;
      *(float2*)&g_feats[r*Dn + col]     = make_float2(tf32_hi(acc[mi][ni][0] + cb[col]), tf32_hi(acc[mi][ni][1] + cb[col+1]));
      *(float2*)&g_feats[(r+8)*Dn + col] = make_float2(tf32_hi(acc[mi][ni][2] + cb[col]), tf32_hi(acc[mi][ni][3] + cb[col+1]));
    }
  }
}

// ---------------- out = relu(feats @ ccW1^T + bias2[b]) ----------------
// Both operands pre-rounded -> no cvt in loop.
__global__ void __launch_bounds__(256,2) k_out(float* __restrict__ out){
  size_t m0 = (size_t)blockIdx.x*128;
  int bb = (int)(m0 >> 11);
  __shared__ float As[2][128][32], Bs[2][128][32];
  __shared__ float b2s[128];
  int tid = threadIdx.x;
  if (tid < 128) b2s[tid] = g_bias2[bb*Dn + tid];
  int arow = tid >> 1, aj0 = (tid & 1)*2;
  int bkl = tid >> 4, bseg = tid & 15;
  // preload chunk 0
  {
    float4 v0 = *(const float4*)&g_feats[(m0 + arow)*(size_t)Dn + aj0*4];
    float4 v1 = *(const float4*)&g_feats[(m0 + arow)*(size_t)Dn + aj0*4 + 4];
    storeA2(As[0], arow, aj0, v0, v1);
    const float* src = &g_ccWT[bkl*128 + bseg*8];
    float4 w0 = *(const float4*)&src[0], w1 = *(const float4*)&src[4];
    float bv[8] = {w0.x,w0.y,w0.z,w0.w,w1.x,w1.y,w1.z,w1.w};
    storeB8(Bs[0], bseg, bkl, bv);
  }
  __syncthreads();
  int warp = tid >> 5, lane = tid & 31;
  int WM = warp >> 1, WN = warp & 1;
  int grp = lane >> 2, qd = lane & 3;
  int mb = WM*32, nb = WN*64;
  float acc[2][8][4] = {};
  for (int k0 = 0; k0 < 8; k0++){
    float4 av0, av1, bv0, bv1;
    bool nxt = (k0 < 7);
    if (nxt){
      int kn = (k0+1)*16;
      av0 = *(const float4*)&g_feats[(m0 + arow)*(size_t)Dn + kn + aj0*4];
      av1 = *(const float4*)&g_feats[(m0 + arow)*(size_t)Dn + kn + aj0*4 + 4];
      const float* sp = &g_ccWT[(kn + bkl)*128 + bseg*8];
      bv0 = *(const float4*)&sp[0]; bv1 = *(const float4*)&sp[4];
    }
    mma_k16(As[k0&1], Bs[k0&1], acc, mb, nb, grp, qd);
    if (nxt){
      int nbuf = (k0+1)&1;
      storeA2(As[nbuf], arow, aj0, av0, av1);
      float bv[8] = {bv0.x,bv0.y,bv0.z,bv0.w,bv1.x,bv1.y,bv1.z,bv1.w};
      storeB8(Bs[nbuf], bseg, bkl, bv);
    }
    __syncthreads();
  }
  #pragma unroll
  for (int mi = 0; mi < 2; mi++){
    size_t r = m0 + mb + mi*16 + grp;
    #pragma unroll
    for (int ni = 0; ni < 8; ni++){
      int col = nb + ni*8 + qd*2;
      float2 w0 = make_float2(fmaxf(acc[mi][ni][0] + b2s[col], 0.f), fmaxf(acc[mi][ni][1] + b2s[col+1], 0.f));
      float2 w1 = make_float2(fmaxf(acc[mi][ni][2] + b2s[col], 0.f), fmaxf(acc[mi][ni][3] + b2s[col+1], 0.f));
      *(float2*)&out[r*Dn + col]     = w0;
      *(float2*)&out[(r+8)*Dn + col] = w1;
    }
  }
}

// ---------------- launch ----------------
extern "C" void kernel_launch(void* const* d_in, const int* in_sizes, int n_in,
                              void* d_out, int out_size){
  const float* vfeats = (const float*)d_in[0];
  const float* qfeats = (const float*)d_in[1];
  const float* vmask  = (const float*)d_in[2];
  const float* qmask  = (const float*)d_in[3];
  const float* w4C    = (const float*)d_in[4];
  const float* w4Q    = (const float*)d_in[5];
  const float* w4mlu  = (const float*)d_in[6];
  const float* cqa_W  = (const float*)d_in[7];
  const float* cqa_b  = (const float*)d_in[8];
  const float* wp     = (const float*)d_in[9];
  const float* cc_W   = (const float*)d_in[10];
  const float* cc_b   = (const float*)d_in[11];
  float* out = (float*)d_out;

  k_prepW<<<256, 256>>>(cqa_W, cc_W, qfeats);
  k_beff<<<Bn, 128>>>(qfeats, w4mlu, w4C);
  k_pool<<<Bn, 128>>>(qfeats, w4Q, wp, qmask, cc_W, cc_b);
  k_score<<<dim3(Cn/128, Bn), 256>>>(vfeats, vmask, qmask);
  k_colcombine<<<Bn, 128>>>();
  k_tmp<<<dim3(4, Bn), 256>>>(vfeats, vmask);
  k_tmp_reduce<<<(Bn*Qn*Dn)/256, 256>>>();
  k_pgemm<0><<<dim3(Cn/128, Bn), 256>>>(qmask);
  k_pgemm<1><<<dim3(Cn/128, Bn), 256>>>(qmask);
  k_feats<<<(Bn*Cn)/128, 256>>>(vfeats, cqa_b);
  k_out<<<(Bn*Cn)/128, 256>>>(out);
}

// round 16
// speedup vs baseline: 1.5270x; 1.0033x over previous
#include <cuda_runtime.h>
#include <math.h>

#define Bn 64
#define Cn 2048
#define Qn 128
#define Dn 128
#define MASK_VAL (-1e30f)

// ---------------- scratch ----------------
__device__ float g_score[(size_t)Bn*Cn*Qn];
__device__ float g_Beff [(size_t)Bn*Dn*Qn];     // tf32-pre-rounded
__device__ float g_bq   [Bn*Qn];
__device__ float g_rowmax[Bn*Cn];
__device__ float g_rowsum[Bn*Cn];
__device__ float g_colpm[Bn*16*Qn];
__device__ float g_colps[Bn*16*Qn];
__device__ float g_colmax[Bn*Qn];
__device__ float g_colsum[Bn*Qn];
__device__ float g_tmp_part[(size_t)Bn*4*Qn*Dn];
__device__ float g_tmp [(size_t)Bn*Qn*Dn];      // tf32-pre-rounded
__device__ float g_bias2[Bn*Dn];
__device__ float g_c2q [(size_t)Bn*Cn*Dn];
__device__ float g_q2c [(size_t)Bn*Cn*Dn];
__device__ float g_feats[(size_t)Bn*Cn*Dn];     // tf32-pre-rounded
__device__ float g_qfT [(size_t)Bn*Qn*Dn];      // tf32-pre-rounded qfeats
__device__ float g_cqaWT[512*128];              // tf32-pre-rounded
__device__ float g_ccWT [128*128];              // tf32-pre-rounded

// ---------------- tf32 helpers ----------------
__device__ __forceinline__ unsigned cvt_tf32(float x){
  unsigned u; asm("cvt.rna.tf32.f32 %0, %1;" : "=r"(u) : "f"(x)); return u;
}
__device__ __forceinline__ float tf32_hi(float x){ return __uint_as_float(cvt_tf32(x)); }

#define MMA_TF32(D, A0,A1,A2,A3, B0,B1) \
  asm volatile("mma.sync.aligned.m16n8k8.row.col.f32.tf32.tf32.f32 " \
      "{%0,%1,%2,%3}, {%4,%5,%6,%7}, {%8,%9}, {%0,%1,%2,%3};" \
      : "+f"(D[0]), "+f"(D[1]), "+f"(D[2]), "+f"(D[3]) \
      : "r"(A0), "r"(A1), "r"(A2), "r"(A3), "r"(B0), "r"(B1))

// ---- swizzled fragment tile [rows][32]:
// element k (0..15) of row n stored at quad ((k&3) + (n&7) + (n>>3)) & 7, offset k>>2.

__device__ __forceinline__ void storeB8(float (*T)[32], int bseg, int bkl, const float* v8){
  int bq = bkl >> 2, bc = bkl & 3;
  int e0 = bseg*8;
  #pragma unroll
  for (int e = 0; e < 8; e++)
    T[e0+e][((bc + e + bseg) & 7)*4 + bq] = v8[e];
}
__device__ __forceinline__ void storeA2(float (*T)[32], int arow, int aj0,
                                        const float4& v0, const float4& v1){
  int ga = (arow & 7) + (arow >> 3);
  const float* p0 = (const float*)&v0;
  const float* p1 = (const float*)&v1;
  #pragma unroll
  for (int t = 0; t < 4; t++){
    T[arow][((t + ga) & 7)*4 + aj0]     = p0[t];
    T[arow][((t + ga) & 7)*4 + aj0 + 1] = p1[t];
  }
}
__device__ __forceinline__ void storeA1(float (*T)[32], int arow, int aj, const float4& v){
  int ga = (arow & 7) + (arow >> 3);
  const float* p = (const float*)&v;
  #pragma unroll
  for (int t = 0; t < 4; t++)
    T[arow][((t + ga) & 7)*4 + aj] = p[t];
}

// Per-warp 32x64 tile MMA over a k16 chunk, swizzled tiles.
__device__ __forceinline__ void mma_k16(const float (*As)[32], const float (*Bs)[32],
                                        float acc[2][8][4], int mb, int nb, int grp, int qd){
  int baseq = qd + grp;
  int mh = mb >> 3, nh = nb >> 3;
  float4 va[2][2];
  #pragma unroll
  for (int mi = 0; mi < 2; mi++){
    int r = mb + mi*16 + grp;
    va[mi][0] = *(const float4*)&As[r][((baseq + mh + mi*2) & 7)*4];
    va[mi][1] = *(const float4*)&As[r+8][((baseq + mh + mi*2 + 1) & 7)*4];
  }
  float4 vb[8];
  #pragma unroll
  for (int ni = 0; ni < 8; ni++){
    int n = nb + ni*8 + grp;
    vb[ni] = *(const float4*)&Bs[n][((baseq + nh + ni) & 7)*4];
  }
  #pragma unroll
  for (int mi = 0; mi < 2; mi++)
    #pragma unroll
    for (int ni = 0; ni < 8; ni++){
      MMA_TF32(acc[mi][ni],
        __float_as_uint(va[mi][0].x), __float_as_uint(va[mi][1].x),
        __float_as_uint(va[mi][0].y), __float_as_uint(va[mi][1].y),
        __float_as_uint(vb[ni].x),    __float_as_uint(vb[ni].y));
      MMA_TF32(acc[mi][ni],
        __float_as_uint(va[mi][0].z), __float_as_uint(va[mi][1].z),
        __float_as_uint(va[mi][0].w), __float_as_uint(va[mi][1].w),
        __float_as_uint(vb[ni].z),    __float_as_uint(vb[ni].w));
    }
}

__device__ __forceinline__ float4 tf4(float4 v){
  return make_float4(tf32_hi(v.x), tf32_hi(v.y), tf32_hi(v.z), tf32_hi(v.w));
}
__device__ __forceinline__ float4 mul4(float4 a, float4 b){
  return make_float4(a.x*b.x, a.y*b.y, a.z*b.z, a.w*b.w);
}

// ---------------- prep kernels ----------------
__global__ void k_prepW(const float* __restrict__ cqaW, const float* __restrict__ ccW,
                        const float* __restrict__ qf){
  int tid = blockIdx.x*blockDim.x + threadIdx.x;
  int stride = gridDim.x*blockDim.x;
  for (int idx = tid; idx < 512*128; idx += stride){
    int k = idx >> 7, n = idx & 127;
    g_cqaWT[idx] = tf32_hi(cqaW[n*512 + k]);
  }
  for (int idx = tid; idx < 128*128; idx += stride){
    int k = idx >> 7, n = idx & 127;
    g_ccWT[idx] = tf32_hi(ccW[n*256 + k]);
  }
  for (int idx = tid; idx < Bn*Qn*Dn; idx += stride)
    g_qfT[idx] = tf32_hi(qf[idx]);
}

__global__ void __launch_bounds__(128) k_beff(const float* __restrict__ qf,
                                              const float* __restrict__ w4mlu,
                                              const float* __restrict__ w4C){
  int b = blockIdx.x, tid = threadIdx.x;
  __shared__ float s[64][129];
  for (int q0 = 0; q0 < Qn; q0 += 64){
    for (int r = 0; r < 64; r++)
      s[r][tid] = qf[((size_t)b*Qn + q0 + r)*Dn + tid];
    __syncthreads();
    for (int it = 0; it < 64; it++){
      int idx = it*128 + tid;
      int d = idx >> 6, q = idx & 63;
      g_Beff[(size_t)b*Dn*Qn + (size_t)d*Qn + q0 + q] = tf32_hi(s[q][d]*w4mlu[d] + w4C[d]);
    }
    __syncthreads();
  }
}

__global__ void __launch_bounds__(128) k_pool(const float* __restrict__ qf,
                                              const float* __restrict__ w4Q,
                                              const float* __restrict__ wp,
                                              const float* __restrict__ qmask,
                                              const float* __restrict__ ccW,
                                              const float* __restrict__ ccb){
  int b = blockIdx.x, tid = threadIdx.x;
  __shared__ float red[128];
  __shared__ float alpha[128];
  __shared__ float pooled[128];
  const float* qrow = qf + ((size_t)b*Qn + tid)*Dn;
  float bq = 0.f, lg = 0.f;
  for (int d = 0; d < Dn; d++){ float v = qrow[d]; bq += v*w4Q[d]; lg += v*wp[d]; }
  g_bq[b*Qn + tid] = bq;
  float x = lg + (1.f - qmask[b*Qn + tid])*MASK_VAL;
  red[tid] = x; __syncthreads();
  for (int s = 64; s > 0; s >>= 1){ if (tid < s) red[tid] = fmaxf(red[tid], red[tid+s]); __syncthreads(); }
  float m = red[0]; __syncthreads();
  float e = __expf(x - m);
  red[tid] = e; __syncthreads();
  for (int s = 64; s > 0; s >>= 1){ if (tid < s) red[tid] += red[tid+s]; __syncthreads(); }
  float ssum = red[0];
  alpha[tid] = e / ssum;
  __syncthreads();
  float p = 0.f;
  for (int q = 0; q < Qn; q++) p += qf[((size_t)b*Qn + q)*Dn + tid]*alpha[q];
  pooled[tid] = p; __syncthreads();
  float acc = ccb[tid];
  for (int k = 0; k < Dn; k++) acc += pooled[k]*ccW[tid*256 + 128 + k];
  g_bias2[b*Dn + tid] = acc;
}

// ---------------- score GEMM (tf32, db, swizzled) + fused softmax stats ----------------
__global__ void __launch_bounds__(256,2) k_score(const float* __restrict__ vfeats,
                                                 const float* __restrict__ vmask,
                                                 const float* __restrict__ qmask){
  int b  = blockIdx.y, bx = blockIdx.x;
  int m0 = bx*128;
  const float* A  = vfeats + (size_t)b*Cn*Dn;
  const float* Bm = g_Beff + (size_t)b*Dn*Qn;   // pre-rounded
  float* Sout = g_score + (size_t)b*Cn*Qn;
  __shared__ float As[2][128][32], Bs[2][128][32];
  __shared__ float bqs[128], qm[128], vm[128];
  __shared__ float smRm[128][2], smRs[128][2];
  __shared__ float smCm[128][4], smCs[128][4];
  int tid = threadIdx.x;
  if (tid < 128){
    bqs[tid] = g_bq[b*Qn + tid];
    qm[tid]  = (1.f - qmask[b*Qn + tid])*MASK_VAL;
    vm[tid]  = (1.f - vmask[b*Cn + m0 + tid])*MASK_VAL;
  }
  int arow = tid >> 1, aj0 = (tid & 1)*2;
  int bkl = tid >> 4, bseg = tid & 15;
  // preload chunk 0
  {
    float4 v0 = tf4(*(const float4*)&A[(size_t)(m0 + arow)*Dn + aj0*4]);
    float4 v1 = tf4(*(const float4*)&A[(size_t)(m0 + arow)*Dn + aj0*4 + 4]);
    storeA2(As[0], arow, aj0, v0, v1);
    const float* src = &Bm[(size_t)bkl*Qn + bseg*8];
    float4 w0 = *(const float4*)&src[0], w1 = *(const float4*)&src[4];
    float vv[8] = {w0.x,w0.y,w0.z,w0.w,w1.x,w1.y,w1.z,w1.w};
    storeB8(Bs[0], bseg, bkl, vv);
  }
  __syncthreads();
  int warp = tid >> 5, lane = tid & 31;
  int WM = warp >> 1, WN = warp & 1;
  int grp = lane >> 2, qd = lane & 3;
  int mb = WM*32, nb = WN*64;
  float acc[2][8][4] = {};
  for (int k0 = 0; k0 < 8; k0++){
    float4 av0, av1, bv0, bv1;
    bool nxt = (k0 < 7);
    if (nxt){
      int kn = (k0+1)*16;
      av0 = *(const float4*)&A[(size_t)(m0 + arow)*Dn + kn + aj0*4];
      av1 = *(const float4*)&A[(size_t)(m0 + arow)*Dn + kn + aj0*4 + 4];
      const float* sp = &Bm[(size_t)(kn + bkl)*Qn + bseg*8];
      bv0 = *(const float4*)&sp[0]; bv1 = *(const float4*)&sp[4];
    }
    mma_k16(As[k0&1], Bs[k0&1], acc, mb, nb, grp, qd);
    if (nxt){
      int nbuf = (k0+1)&1;
      storeA2(As[nbuf], arow, aj0, tf4(av0), tf4(av1));
      float vv[8] = {bv0.x,bv0.y,bv0.z,bv0.w,bv1.x,bv1.y,bv1.z,bv1.w};
      storeB8(Bs[nbuf], bseg, bkl, vv);
    }
    __syncthreads();
  }
  // ---- epilogue: add bq, write score, fused row/col softmax stats ----
  #pragma unroll
  for (int mi = 0; mi < 2; mi++){
    int r = m0 + mb + mi*16 + grp;
    #pragma unroll
    for (int ni = 0; ni < 8; ni++){
      int c0 = nb + ni*8 + qd*2;
      acc[mi][ni][0] += bqs[c0]; acc[mi][ni][1] += bqs[c0+1];
      acc[mi][ni][2] += bqs[c0]; acc[mi][ni][3] += bqs[c0+1];
      *(float2*)&Sout[(size_t)r*Qn + c0]     = make_float2(acc[mi][ni][0], acc[mi][ni][1]);
      *(float2*)&Sout[(size_t)(r+8)*Qn + c0] = make_float2(acc[mi][ni][2], acc[mi][ni][3]);
    }
  }
  // row stats
  #pragma unroll
  for (int s = 0; s < 4; s++){
    int mi = s >> 1, e0 = (s & 1)*2;
    float m = -INFINITY;
    #pragma unroll
    for (int ni = 0; ni < 8; ni++){
      int c0 = nb + ni*8 + qd*2;
      m = fmaxf(m, acc[mi][ni][e0]   + qm[c0]);
      m = fmaxf(m, acc[mi][ni][e0+1] + qm[c0+1]);
    }
    m = fmaxf(m, __shfl_xor_sync(0xffffffffu, m, 1));
    m = fmaxf(m, __shfl_xor_sync(0xffffffffu, m, 2));
    float ssum = 0.f;
    #pragma unroll
    for (int ni = 0; ni < 8; ni++){
      int c0 = nb + ni*8 + qd*2;
      ssum += __expf(acc[mi][ni][e0]   + qm[c0]   - m);
      ssum += __expf(acc[mi][ni][e0+1] + qm[c0+1] - m);
    }
    ssum += __shfl_xor_sync(0xffffffffu, ssum, 1);
    ssum += __shfl_xor_sync(0xffffffffu, ssum, 2);
    if (qd == 0){
      int rr = mb + mi*16 + (s & 1)*8 + grp;
      smRm[rr][WN] = m; smRs[rr][WN] = ssum;
    }
  }
  // col stats (partial over this block's 128 rows)
  float vmr[4] = { vm[mb+grp], vm[mb+grp+8], vm[mb+16+grp], vm[mb+16+grp+8] };
  #pragma unroll
  for (int g = 0; g < 4; g++){
    float cm4[4], cs4[4];
    #pragma unroll
    for (int u = 0; u < 4; u++){
      int idx = g*4 + u;
      int ni = idx >> 1, e = idx & 1;
      float m = fmaxf(fmaxf(acc[0][ni][e] + vmr[0], acc[0][ni][e+2] + vmr[1]),
                      fmaxf(acc[1][ni][e] + vmr[2], acc[1][ni][e+2] + vmr[3]));
      cm4[u] = m;
    }
    #pragma unroll
    for (int o = 4; o <= 16; o <<= 1)
      #pragma unroll
      for (int u = 0; u < 4; u++)
        cm4[u] = fmaxf(cm4[u], __shfl_xor_sync(0xffffffffu, cm4[u], o));
    #pragma unroll
    for (int u = 0; u < 4; u++){
      int idx = g*4 + u;
      int ni = idx >> 1, e = idx & 1;
      cs4[u] = __expf(acc[0][ni][e]   + vmr[0] - cm4[u])
             + __expf(acc[0][ni][e+2] + vmr[1] - cm4[u])
             + __expf(acc[1][ni][e]   + vmr[2] - cm4[u])
             + __expf(acc[1][ni][e+2] + vmr[3] - cm4[u]);
    }
    #pragma unroll
    for (int o = 4; o <= 16; o <<= 1)
      #pragma unroll
      for (int u = 0; u < 4; u++)
        cs4[u] += __shfl_xor_sync(0xffffffffu, cs4[u], o);
    if (grp == 0){
      #pragma unroll
      for (int u = 0; u < 4; u++){
        int idx = g*4 + u;
        int ni = idx >> 1, e = idx & 1;
        int col = nb + ni*8 + qd*2 + e;
        smCm[col][WM] = cm4[u]; smCs[col][WM] = cs4[u];
      }
    }
  }
  __syncthreads();
  if (tid < 128){
    float ma = smRm[tid][0], mbv = smRm[tid][1];
    float M = fmaxf(ma, mbv);
    float S = smRs[tid][0]*__expf(ma - M) + smRs[tid][1]*__expf(mbv - M);
    g_rowmax[b*Cn + m0 + tid] = M;
    g_rowsum[b*Cn + m0 + tid] = S;
    float cm2 = -INFINITY, cs2 = 0.f;
    #pragma unroll
    for (int w = 0; w < 4; w++){
      float pm = smCm[tid][w], ps = smCs[tid][w];
      float nm = fmaxf(cm2, pm);
      cs2 = cs2*__expf(cm2 - nm) + ps*__expf(pm - nm);
      cm2 = nm;
    }
    g_colpm[(b*16 + bx)*Qn + tid] = cm2;
    g_colps[(b*16 + bx)*Qn + tid] = cs2;
  }
}

__global__ void __launch_bounds__(128) k_colcombine(){
  int b = blockIdx.x, q = threadIdx.x;
  float m = -INFINITY, s = 0.f;
  for (int ch = 0; ch < 16; ch++){
    float pm = g_colpm[(b*16 + ch)*Qn + q];
    float ps = g_colps[(b*16 + ch)*Qn + q];
    float nm = fmaxf(m, pm);
    s = s*__expf(m - nm) + ps*__expf(pm - nm);
    m = nm;
  }
  g_colmax[b*Qn + q] = m;
  g_colsum[b*Qn + q] = s;
}

// ---------------- tmp = score_t^T @ V (tf32, split-K x4, db, swizzled) ----------------
__global__ void __launch_bounds__(256,2) k_tmp(const float* __restrict__ vfeats,
                                               const float* __restrict__ vmask){
  int b = blockIdx.y, ch = blockIdx.x;
  const float* Sb = g_score + (size_t)b*Cn*Qn;
  const float* V  = vfeats  + (size_t)b*Cn*Dn;
  __shared__ float As[2][128][32], Bs[2][128][32];
  __shared__ float cm[128];
  int tid = threadIdx.x;
  if (tid < 128) cm[tid] = g_colmax[b*Qn + tid];
  __syncthreads();
  int bkl = tid >> 4, bseg = tid & 15;
  int e0 = bseg*8;
  int cbase = ch*512;
  // preload chunk 0
  {
    int c = cbase + bkl;
    float mv = (1.f - vmask[b*Cn + c])*MASK_VAL;
    float4 s0 = *(const float4*)&Sb[(size_t)c*Qn + e0];
    float4 s1 = *(const float4*)&Sb[(size_t)c*Qn + e0 + 4];
    float av[8] = {tf32_hi(__expf(s0.x+mv-cm[e0+0])), tf32_hi(__expf(s0.y+mv-cm[e0+1])),
                   tf32_hi(__expf(s0.z+mv-cm[e0+2])), tf32_hi(__expf(s0.w+mv-cm[e0+3])),
                   tf32_hi(__expf(s1.x+mv-cm[e0+4])), tf32_hi(__expf(s1.y+mv-cm[e0+5])),
                   tf32_hi(__expf(s1.z+mv-cm[e0+6])), tf32_hi(__expf(s1.w+mv-cm[e0+7]))};
    storeB8(As[0], bseg, bkl, av);
    float4 v0 = *(const float4*)&V[(size_t)c*Dn + e0];
    float4 v1 = *(const float4*)&V[(size_t)c*Dn + e0 + 4];
    float bv[8] = {tf32_hi(v0.x),tf32_hi(v0.y),tf32_hi(v0.z),tf32_hi(v0.w),
                   tf32_hi(v1.x),tf32_hi(v1.y),tf32_hi(v1.z),tf32_hi(v1.w)};
    storeB8(Bs[0], bseg, bkl, bv);
  }
  __syncthreads();
  int warp = tid >> 5, lane = tid & 31;
  int WM = warp >> 1, WN = warp & 1;
  int grp = lane >> 2, qd = lane & 3;
  int mb = WM*32, nb = WN*64;
  float acc[2][8][4] = {};
  for (int kt = 0; kt < 32; kt++){
    float4 s0n, s1n, v0n, v1n; float mvn = 0.f;
    bool nxt = (kt < 31);
    if (nxt){
      int c = cbase + (kt+1)*16 + bkl;
      mvn = (1.f - vmask[b*Cn + c])*MASK_VAL;
      s0n = *(const float4*)&Sb[(size_t)c*Qn + e0];
      s1n = *(const float4*)&Sb[(size_t)c*Qn + e0 + 4];
      v0n = *(const float4*)&V[(size_t)c*Dn + e0];
      v1n = *(const float4*)&V[(size_t)c*Dn + e0 + 4];
    }
    mma_k16(As[kt&1], Bs[kt&1], acc, mb, nb, grp, qd);
    if (nxt){
      int nbuf = (kt+1)&1;
      float av[8] = {tf32_hi(__expf(s0n.x+mvn-cm[e0+0])), tf32_hi(__expf(s0n.y+mvn-cm[e0+1])),
                     tf32_hi(__expf(s0n.z+mvn-cm[e0+2])), tf32_hi(__expf(s0n.w+mvn-cm[e0+3])),
                     tf32_hi(__expf(s1n.x+mvn-cm[e0+4])), tf32_hi(__expf(s1n.y+mvn-cm[e0+5])),
                     tf32_hi(__expf(s1n.z+mvn-cm[e0+6])), tf32_hi(__expf(s1n.w+mvn-cm[e0+7]))};
      storeB8(As[nbuf], bseg, bkl, av);
      float bv[8] = {tf32_hi(v0n.x),tf32_hi(v0n.y),tf32_hi(v0n.z),tf32_hi(v0n.w),
                     tf32_hi(v1n.x),tf32_hi(v1n.y),tf32_hi(v1n.z),tf32_hi(v1n.w)};
      storeB8(Bs[nbuf], bseg, bkl, bv);
    }
    __syncthreads();
  }
  float* P = g_tmp_part + (size_t)(b*4 + ch)*Qn*Dn;
  #pragma unroll
  for (int mi = 0; mi < 2; mi++){
    int r = mb + mi*16 + grp;
    #pragma unroll
    for (int ni = 0; ni < 8; ni++){
      int col = nb + ni*8 + qd*2;
      *(float2*)&P[(size_t)r*Dn + col]     = make_float2(acc[mi][ni][0], acc[mi][ni][1]);
      *(float2*)&P[(size_t)(r+8)*Dn + col] = make_float2(acc[mi][ni][2], acc[mi][ni][3]);
    }
  }
}

__global__ void __launch_bounds__(256) k_tmp_reduce(){
  int idx = blockIdx.x*256 + threadIdx.x;
  int b = idx >> 14;
  int r = idx & 16383;
  int q = r >> 7;
  size_t base = (size_t)b*4*Qn*Dn + r;
  float s = g_tmp_part[base] + g_tmp_part[base + Qn*Dn]
          + g_tmp_part[base + 2*Qn*Dn] + g_tmp_part[base + 3*Qn*Dn];
  g_tmp[idx] = tf32_hi(s / g_colsum[b*Qn + q]);
}

// ---------------- fused P @ [qfT | tmp] -> c2q, q2c ----------------
// Block tile 64 x 256 (N-concat). Score read + softmax exp happen ONCE.
// Warp tiles stay 32x64 (acc=64 regs). WN 0,1 -> c2q cols 0..127; WN 2,3 -> q2c.
// Math/operand bits per output identical to the previous split kernels.
__global__ void __launch_bounds__(256,2) k_pgemmN(const float* __restrict__ qmask){
  int b = blockIdx.y; int m0 = blockIdx.x*64;
  const float* Sb = g_score + (size_t)b*Cn*Qn;
  const float* B1 = g_qfT + (size_t)b*Qn*Dn;
  const float* B2 = g_tmp + (size_t)b*Qn*Dn;
  __shared__ float As[2][64][32], Bs[2][256][32];
  __shared__ float qm[128], rm[64], ri[64];
  int tid = threadIdx.x;
  if (tid < 128) qm[tid] = (1.f - qmask[b*Qn + tid])*MASK_VAL;
  if (tid < 64){
    rm[tid] = g_rowmax[b*Cn + m0 + tid];
    ri[tid] = 1.f / g_rowsum[b*Cn + m0 + tid];
  }
  __syncthreads();
  int arow = tid >> 2, aj = tid & 3;
  int bkl8 = tid >> 5, bsegF = tid & 31;              // bsegF<16 -> B1 rows, else B2
  const float* Bsrc = (bsegF < 16) ? B1 : B2;
  int bcol0 = (bsegF & 15)*8;
  float mm = rm[arow], rr = ri[arow];
  // preload chunk 0
  {
    int kg = aj*4;
    float4 v = *(const float4*)&Sb[(size_t)(m0 + arow)*Qn + kg];
    float4 a = make_float4(tf32_hi(__expf(v.x + qm[kg]   - mm)*rr),
                           tf32_hi(__expf(v.y + qm[kg+1] - mm)*rr),
                           tf32_hi(__expf(v.z + qm[kg+2] - mm)*rr),
                           tf32_hi(__expf(v.w + qm[kg+3] - mm)*rr));
    storeA1(As[0], arow, aj, a);
    #pragma unroll
    for (int h = 0; h < 2; h++){
      int bkl = bkl8 + h*8;
      const float* sp = &Bsrc[(size_t)bkl*Dn + bcol0];
      float4 w0 = *(const float4*)&sp[0], w1 = *(const float4*)&sp[4];
      float bv[8] = {w0.x,w0.y,w0.z,w0.w,w1.x,w1.y,w1.z,w1.w};
      storeB8(Bs[0], bsegF, bkl, bv);
    }
  }
  __syncthreads();
  int warp = tid >> 5, lane = tid & 31;
  int WM = warp >> 2, WN = warp & 3;
  int grp = lane >> 2, qd = lane & 3;
  int mb = WM*32, nb = WN*64;
  float acc[2][8][4] = {};
  for (int k0 = 0; k0 < 8; k0++){
    float4 av, w0a, w1a, w0b, w1b;
    bool nxt = (k0 < 7);
    if (nxt){
      int kn = (k0+1)*16;
      av = *(const float4*)&Sb[(size_t)(m0 + arow)*Qn + kn + aj*4];
      const float* spa = &Bsrc[(size_t)(kn + bkl8)*Dn + bcol0];
      w0a = *(const float4*)&spa[0]; w1a = *(const float4*)&spa[4];
      const float* spb = &Bsrc[(size_t)(kn + bkl8 + 8)*Dn + bcol0];
      w0b = *(const float4*)&spb[0]; w1b = *(const float4*)&spb[4];
    }
    mma_k16(As[k0&1], Bs[k0&1], acc, mb, nb, grp, qd);
    if (nxt){
      int nbuf = (k0+1)&1;
      int kg = (k0+1)*16 + aj*4;
      float4 a = make_float4(tf32_hi(__expf(av.x + qm[kg]   - mm)*rr),
                             tf32_hi(__expf(av.y + qm[kg+1] - mm)*rr),
                             tf32_hi(__expf(av.z + qm[kg+2] - mm)*rr),
                             tf32_hi(__expf(av.w + qm[kg+3] - mm)*rr));
      storeA1(As[nbuf], arow, aj, a);
      float bva[8] = {w0a.x,w0a.y,w0a.z,w0a.w,w1a.x,w1a.y,w1a.z,w1a.w};
      storeB8(Bs[nbuf], bsegF, bkl8, bva);
      float bvb[8] = {w0b.x,w0b.y,w0b.z,w0b.w,w1b.x,w1b.y,w1b.z,w1b.w};
      storeB8(Bs[nbuf], bsegF, bkl8 + 8, bvb);
    }
    __syncthreads();
  }
  float* O = (WN < 2 ? g_c2q : g_q2c) + ((size_t)b*Cn + m0)*Dn;
  int nbo = (WN & 1)*64;
  #pragma unroll
  for (int mi = 0; mi < 2; mi++){
    int r = mb + mi*16 + grp;
    #pragma unroll
    for (int ni = 0; ni < 8; ni++){
      int col = nbo + ni*8 + qd*2;
      *(float2*)&O[(size_t)r*Dn + col]     = make_float2(acc[mi][ni][0], acc[mi][ni][1]);
      *(float2*)&O[(size_t)(r+8)*Dn + col] = make_float2(acc[mi][ni][2], acc[mi][ni][3]);
    }
  }
}

// ---------------- feats = [v, c2q, v*c2q, v*q2c] @ cqa_W^T + b ----------------
__global__ void __launch_bounds__(256,2) k_feats(const float* __restrict__ vfeats,
                                                 const float* __restrict__ cqa_b){
  size_t m0 = (size_t)blockIdx.x*128;
  __shared__ float As[2][128][32], Bs[2][128][32];
  __shared__ float cb[128];
  int tid = threadIdx.x;
  if (tid < 128) cb[tid] = cqa_b[tid];
  int arow = tid >> 1, aj0 = (tid & 1)*2;
  int bkl = tid >> 4, bseg = tid & 15;
  float4 vk0, vk1, ck0, ck1;
  // preload it=0: g=0, s=0 -> vfeats chunk 0
  {
    size_t off0 = (m0 + arow)*(size_t)Dn + aj0*4;
    vk0 = *(const float4*)&vfeats[off0];
    vk1 = *(const float4*)&vfeats[off0+4];
    storeA2(As[0], arow, aj0, tf4(vk0), tf4(vk1));
    const float* srcp = &g_cqaWT[bkl*128 + bseg*8];
    float4 w0 = *(const float4*)&srcp[0], w1 = *(const float4*)&srcp[4];
    float bv[8] = {w0.x,w0.y,w0.z,w0.w,w1.x,w1.y,w1.z,w1.w};
    storeB8(Bs[0], bseg, bkl, bv);
  }
  __syncthreads();
  int warp = tid >> 5, lane = tid & 31;
  int WM = warp >> 1, WN = warp & 1;
  int grp = lane >> 2, qd = lane & 3;
  int mb = WM*32, nb = WN*64;
  float acc[2][8][4] = {};
  #pragma unroll 4
  for (int it = 0; it < 32; it++){
    float4 av0, av1, bv0, bv1;
    int it2 = it + 1, g2 = it2 >> 2, s2 = it2 & 3;
    bool nxt = (it < 31);
    if (nxt){
      size_t off0 = (m0 + arow)*(size_t)Dn + g2*16 + aj0*4;
      if (s2 == 0)      { av0 = *(const float4*)&vfeats[off0]; av1 = *(const float4*)&vfeats[off0+4]; }
      else if (s2 == 1) { av0 = *(const float4*)&g_c2q[off0];  av1 = *(const float4*)&g_c2q[off0+4]; }
      else if (s2 == 3) { av0 = *(const float4*)&g_q2c[off0];  av1 = *(const float4*)&g_q2c[off0+4]; }
      const float* sp = &g_cqaWT[(s2*128 + g2*16 + bkl)*128 + bseg*8];
      bv0 = *(const float4*)&sp[0]; bv1 = *(const float4*)&sp[4];
    }
    mma_k16(As[it&1], Bs[it&1], acc, mb, nb, grp, qd);
    if (nxt){
      int nbuf = it2 & 1;
      float4 a0, a1;
      if (s2 == 0)      { vk0 = av0; vk1 = av1; a0 = av0; a1 = av1; }
      else if (s2 == 1) { ck0 = av0; ck1 = av1; a0 = av0; a1 = av1; }
      else if (s2 == 2) { a0 = mul4(vk0, ck0); a1 = mul4(vk1, ck1); }
      else              { a0 = mul4(vk0, av0); a1 = mul4(vk1, av1); }
      storeA2(As[nbuf], arow, aj0, tf4(a0), tf4(a1));
      float bv[8] = {bv0.x,bv0.y,bv0.z,bv0.w,bv1.x,bv1.y,bv1.z,bv1.w};
      storeB8(Bs[nbuf], bseg, bkl, bv);
    }
    __syncthreads();
  }
  #pragma unroll
  for (int mi = 0; mi < 2; mi++){
    size_t r = m0 + mb + mi*16 + grp;
    #pragma unroll
    for (int ni = 0; ni < 8; ni++){
      int col = nb + ni*8 + qd*2;
      *(float2*)&g_feats[r*Dn + col]     = make_float2(tf32_hi(acc[mi][ni][0] + cb[col]), tf32_hi(acc[mi][ni][1] + cb[col+1]));
      *(float2*)&g_feats[(r+8)*Dn + col] = make_float2(tf32_hi(acc[mi][ni][2] + cb[col]), tf32_hi(acc[mi][ni][3] + cb[col+1]));
    }
  }
}

// ---------------- out = relu(feats @ ccW1^T + bias2[b]) ----------------
__global__ void __launch_bounds__(256,2) k_out(float* __restrict__ out){
  size_t m0 = (size_t)blockIdx.x*128;
  int bb = (int)(m0 >> 11);
  __shared__ float As[2][128][32], Bs[2][128][32];
  __shared__ float b2s[128];
  int tid = threadIdx.x;
  if (tid < 128) b2s[tid] = g_bias2[bb*Dn + tid];
  int arow = tid >> 1, aj0 = (tid & 1)*2;
  int bkl = tid >> 4, bseg = tid & 15;
  // preload chunk 0
  {
    float4 v0 = *(const float4*)&g_feats[(m0 + arow)*(size_t)Dn + aj0*4];
    float4 v1 = *(const float4*)&g_feats[(m0 + arow)*(size_t)Dn + aj0*4 + 4];
    storeA2(As[0], arow, aj0, v0, v1);
    const float* src = &g_ccWT[bkl*128 + bseg*8];
    float4 w0 = *(const float4*)&src[0], w1 = *(const float4*)&src[4];
    float bv[8] = {w0.x,w0.y,w0.z,w0.w,w1.x,w1.y,w1.z,w1.w};
    storeB8(Bs[0], bseg, bkl, bv);
  }
  __syncthreads();
  int warp = tid >> 5, lane = tid & 31;
  int WM = warp >> 1, WN = warp & 1;
  int grp = lane >> 2, qd = lane & 3;
  int mb = WM*32, nb = WN*64;
  float acc[2][8][4] = {};
  for (int k0 = 0; k0 < 8; k0++){
    float4 av0, av1, bv0, bv1;
    bool nxt = (k0 < 7);
    if (nxt){
      int kn = (k0+1)*16;
      av0 = *(const float4*)&g_feats[(m0 + arow)*(size_t)Dn + kn + aj0*4];
      av1 = *(const float4*)&g_feats[(m0 + arow)*(size_t)Dn + kn + aj0*4 + 4];
      const float* sp = &g_ccWT[(kn + bkl)*128 + bseg*8];
      bv0 = *(const float4*)&sp[0]; bv1 = *(const float4*)&sp[4];
    }
    mma_k16(As[k0&1], Bs[k0&1], acc, mb, nb, grp, qd);
    if (nxt){
      int nbuf = (k0+1)&1;
      storeA2(As[nbuf], arow, aj0, av0, av1);
      float bv[8] = {bv0.x,bv0.y,bv0.z,bv0.w,bv1.x,bv1.y,bv1.z,bv1.w};
      storeB8(Bs[nbuf], bseg, bkl, bv);
    }
    __syncthreads();
  }
  #pragma unroll
  for (int mi = 0; mi < 2; mi++){
    size_t r = m0 + mb + mi*16 + grp;
    #pragma unroll
    for (int ni = 0; ni < 8; ni++){
      int col = nb + ni*8 + qd*2;
      float2 w0 = make_float2(fmaxf(acc[mi][ni][0] + b2s[col], 0.f), fmaxf(acc[mi][ni][1] + b2s[col+1], 0.f));
      float2 w1 = make_float2(fmaxf(acc[mi][ni][2] + b2s[col], 0.f), fmaxf(acc[mi][ni][3] + b2s[col+1], 0.f));
      *(float2*)&out[r*Dn + col]     = w0;
      *(float2*)&out[(r+8)*Dn + col] = w1;
    }
  }
}

// ---------------- launch ----------------
extern "C" void kernel_launch(void* const* d_in, const int* in_sizes, int n_in,
                              void* d_out, int out_size){
  const float* vfeats = (const float*)d_in[0];
  const float* qfeats = (const float*)d_in[1];
  const float* vmask  = (const float*)d_in[2];
  const float* qmask  = (const float*)d_in[3];
  const float* w4C    = (const float*)d_in[4];
  const float* w4Q    = (const float*)d_in[5];
  const float* w4mlu  = (const float*)d_in[6];
  const float* cqa_W  = (const float*)d_in[7];
  const float* cqa_b  = (const float*)d_in[8];
  const float* wp     = (const float*)d_in[9];
  const float* cc_W   = (const float*)d_in[10];
  const float* cc_b   = (const float*)d_in[11];
  float* out = (float*)d_out;

  k_prepW<<<256, 256>>>(cqa_W, cc_W, qfeats);
  k_beff<<<Bn, 128>>>(qfeats, w4mlu, w4C);
  k_pool<<<Bn, 128>>>(qfeats, w4Q, wp, qmask, cc_W, cc_b);
  k_score<<<dim3(Cn/128, Bn), 256>>>(vfeats, vmask, qmask);
  k_colcombine<<<Bn, 128>>>();
  k_tmp<<<dim3(4, Bn), 256>>>(vfeats, vmask);
  k_tmp_reduce<<<(Bn*Qn*Dn)/256, 256>>>();
  k_pgemmN<<<dim3(Cn/64, Bn), 256>>>(qmask);
  k_feats<<<(Bn*Cn)/128, 256>>>(vfeats, cqa_b);
  k_out<<<(Bn*Cn)/128, 256>>>(out);
}